// round 13
// baseline (speedup 1.0000x reference)
#include <cuda_runtime.h>
#include <math.h>

#define TS 2048
#define NCH 256
#define CHSZ 8
#define ESTR 128
#define oA 0
#define oB 36
#define oC 42
#define oE 78
#define oJ 84
#define LOG2PI 1.8378770664093454836

__device__ float g_loc[TS*ESTR];
__device__ float g_agg[2][NCH*ESTR];
__device__ double g_llp[160];

template<typename T> __device__ __forceinline__ T tabs(T x){ return x < T(0) ? -x : x; }

__device__ __forceinline__ float inv4f(const float A[4][4], float R[4][4]) {
    float a00=A[0][0],a01=A[0][1],a02=A[0][2],a03=A[0][3];
    float a10=A[1][0],a11=A[1][1],a12=A[1][2],a13=A[1][3];
    float a20=A[2][0],a21=A[2][1],a22=A[2][2],a23=A[2][3];
    float a30=A[3][0],a31=A[3][1],a32=A[3][2],a33=A[3][3];
    float s0=a00*a11-a10*a01,s1=a00*a12-a10*a02,s2=a00*a13-a10*a03;
    float s3=a01*a12-a11*a02,s4=a01*a13-a11*a03,s5=a02*a13-a12*a03;
    float c5=a22*a33-a32*a23,c4=a21*a33-a31*a23,c3=a21*a32-a31*a22;
    float c2=a20*a33-a30*a23,c1=a20*a32-a30*a22,c0=a20*a31-a30*a21;
    float det=s0*c5-s1*c4+s2*c3+s3*c2-s4*c1+s5*c0;
    float id=__fdividef(1.0f,det);
    R[0][0]=( a11*c5-a12*c4+a13*c3)*id; R[0][1]=(-a01*c5+a02*c4-a03*c3)*id;
    R[0][2]=( a31*s5-a32*s4+a33*s3)*id; R[0][3]=(-a21*s5+a22*s4-a23*s3)*id;
    R[1][0]=(-a10*c5+a12*c2-a13*c1)*id; R[1][1]=( a00*c5-a02*c2+a03*c1)*id;
    R[1][2]=(-a30*s5+a32*s2-a33*s1)*id; R[1][3]=( a20*s5-a22*s2+a23*s1)*id;
    R[2][0]=( a10*c4-a11*c2+a13*c0)*id; R[2][1]=(-a00*c4+a01*c2-a03*c0)*id;
    R[2][2]=( a30*s4-a31*s2+a33*s0)*id; R[2][3]=(-a20*s4+a21*s2-a23*s0)*id;
    R[3][0]=(-a10*c3+a11*c1-a12*c0)*id; R[3][1]=( a00*c3-a01*c1+a02*c0)*id;
    R[3][2]=(-a30*s3+a31*s1-a32*s0)*id; R[3][3]=( a20*s3-a21*s1+a22*s0)*id;
    return det;
}

__device__ __forceinline__ double inv4d(const double A[4][4], double R[4][4]) {
    double a00=A[0][0],a01=A[0][1],a02=A[0][2],a03=A[0][3];
    double a10=A[1][0],a11=A[1][1],a12=A[1][2],a13=A[1][3];
    double a20=A[2][0],a21=A[2][1],a22=A[2][2],a23=A[2][3];
    double a30=A[3][0],a31=A[3][1],a32=A[3][2],a33=A[3][3];
    double s0=a00*a11-a10*a01,s1=a00*a12-a10*a02,s2=a00*a13-a10*a03;
    double s3=a01*a12-a11*a02,s4=a01*a13-a11*a03,s5=a02*a13-a12*a03;
    double c5=a22*a33-a32*a23,c4=a21*a33-a31*a23,c3=a21*a32-a31*a22;
    double c2=a20*a33-a30*a23,c1=a20*a32-a30*a22,c0=a20*a31-a30*a21;
    double det=s0*c5-s1*c4+s2*c3+s3*c2-s4*c1+s5*c0;
    double id=1.0/det;
    R[0][0]=( a11*c5-a12*c4+a13*c3)*id; R[0][1]=(-a01*c5+a02*c4-a03*c3)*id;
    R[0][2]=( a31*s5-a32*s4+a33*s3)*id; R[0][3]=(-a21*s5+a22*s4-a23*s3)*id;
    R[1][0]=(-a10*c5+a12*c2-a13*c1)*id; R[1][1]=( a00*c5-a02*c2+a03*c1)*id;
    R[1][2]=(-a30*s5+a32*s2-a33*s1)*id; R[1][3]=( a20*s5-a22*s2+a23*s1)*id;
    R[2][0]=( a10*c4-a11*c2+a13*c0)*id; R[2][1]=(-a00*c4+a01*c2-a03*c0)*id;
    R[2][2]=( a30*s4-a31*s2+a33*s0)*id; R[2][3]=(-a20*s4+a21*s2-a23*s0)*id;
    R[3][0]=(-a10*c3+a11*c1-a12*c0)*id; R[3][1]=( a00*c3-a01*c1+a02*c0)*id;
    R[3][2]=(-a30*s3+a31*s1-a32*s0)*id; R[3][3]=( a20*s3-a21*s1+a22*s0)*id;
    return det;
}

// Row-parallel Sarkka composition; NOINLINE so each kernel carries ONE copy
// (body-size < 32KB defeats the low-occupancy issue throttle).
template<typename T, bool VEC>
__device__ __noinline__ void compose_rp(
    unsigned mask, int base, int r,
    const T* A1, const T* C1, const T* J1, const T* b1, const T* e1,
    const T* A2, const T* C2, const T* J2, const T* b2, const T* e2,
    T* Ao, T* Co, T* Jo, T* bo, T* eo)
{
    T M[12];
#pragma unroll
    for (int c=0;c<6;++c){
        T s=(r==c)?T(1):T(0);
#pragma unroll
        for (int k=0;k<6;++k) s += C1[k]*__shfl_sync(mask, J2[c], base+k);
        M[c]=s; M[6+c]=(r==c)?T(1):T(0);
    }
#pragma unroll
    for (int col=0;col<6;++col){
        T v = (r>=col)?tabs(M[col]):T(-1);
        int p=col; T bv=__shfl_sync(mask, v, base+col);
#pragma unroll
        for (int rr=0;rr<6;++rr){
            T vv=__shfl_sync(mask, v, base+rr);
            if (rr>col && vv>bv){ bv=vv; p=rr; }
        }
        int src = (r==col)?p:((r==p)?col:r);
#pragma unroll
        for (int j=0;j<12;++j) M[j]=__shfl_sync(mask, M[j], base+src);
        T piv=__shfl_sync(mask, M[col], base+col);
        T ip=T(1)/piv;
        if (r==col){
#pragma unroll
            for (int j=0;j<12;++j) M[j]*=ip;
        }
        T f=M[col];
        T pr[12];
#pragma unroll
        for (int j=0;j<12;++j) pr[j]=__shfl_sync(mask, M[j], base+col);
        if (r!=col){
#pragma unroll
            for (int j=0;j<12;++j) M[j]-=f*pr[j];
        }
    }
    T D[6];
#pragma unroll
    for (int c=0;c<6;++c) D[c]=M[6+c];
    T T1[6];
#pragma unroll
    for (int c=0;c<6;++c){ T s=T(0);
#pragma unroll
        for (int k=0;k<6;++k) s+=D[k]*__shfl_sync(mask, A1[c], base+k);
        T1[c]=s; }
#pragma unroll
    for (int c=0;c<6;++c){ T s=T(0);
#pragma unroll
        for (int k=0;k<6;++k) s+=A2[k]*__shfl_sync(mask, T1[c], base+k);
        Ao[c]=s; }
    if (VEC) {
        T u[6], wv[6];
#pragma unroll
        for (int i=0;i<6;++i){ T s=b1[i];
#pragma unroll
            for (int k=0;k<6;++k) s+=__shfl_sync(mask, C1[k], base+i)*e2[k];
            u[i]=s; }
#pragma unroll
        for (int i=0;i<6;++i){ T s=T(0);
#pragma unroll
            for (int k=0;k<6;++k) s+=__shfl_sync(mask, D[k], base+i)*u[k];
            wv[i]=s; }
#pragma unroll
        for (int i=0;i<6;++i){ T s=b2[i];
#pragma unroll
            for (int k=0;k<6;++k) s+=__shfl_sync(mask, A2[k], base+i)*wv[k];
            bo[i]=s; }
        T rv[6];
#pragma unroll
        for (int k=0;k<6;++k){ T s=e2[k];
#pragma unroll
            for (int m=0;m<6;++m) s-=__shfl_sync(mask, J2[m], base+k)*b1[m];
            rv[k]=s; }
#pragma unroll
        for (int c=0;c<6;++c){ T s=e1[c];
#pragma unroll
            for (int k=0;k<6;++k) s+=__shfl_sync(mask, T1[c], base+k)*rv[k];
            eo[c]=s; }
    }
    T S[6], Tt[6];
#pragma unroll
    for (int c=0;c<6;++c){ T s=T(0);
#pragma unroll
        for (int k=0;k<6;++k) s+=D[k]*__shfl_sync(mask, C1[c], base+k);
        S[c]=s; }
#pragma unroll
    for (int c=0;c<6;++c){ T s=T(0);
#pragma unroll
        for (int k=0;k<6;++k) s+=A2[k]*__shfl_sync(mask, S[c], base+k);
        Tt[c]=s; }
#pragma unroll
    for (int c=0;c<6;++c){ T s=C2[c];
#pragma unroll
        for (int k=0;k<6;++k) s+=Tt[k]*__shfl_sync(mask, A2[k], base+c);
        Co[c]=s; }
    T T5[6];
#pragma unroll
    for (int c=0;c<6;++c){ T s=T(0);
#pragma unroll
        for (int k=0;k<6;++k) s+=J2[k]*__shfl_sync(mask, A1[c], base+k);
        T5[c]=s; }
    T T1t[6];
#pragma unroll
    for (int j=0;j<6;++j){
#pragma unroll
        for (int k=0;k<6;++k){
            T w2=__shfl_sync(mask, T1[j], base+k);
            if (r==j) T1t[k]=w2;
        }
    }
#pragma unroll
    for (int c=0;c<6;++c){ T s=J1[c];
#pragma unroll
        for (int k=0;k<6;++k) s+=T1t[k]*__shfl_sync(mask, T5[c], base+k);
        Jo[c]=s; }
}

__device__ __noinline__ void build_step(
    int r, float y0, float y1,
    const float Si[4][4], const float K2[2][4], const float C2m[2][2],
    float* A, float* C, float* J, float* b, float* e)
{
    float yb[4]={y0,y1,y0,y1};
#pragma unroll
    for (int c=0;c<6;++c){ A[c]=(r==c)?1.0f:0.0f; C[c]=0.0f; }
    if (r==4) A[5]=1.0f;
    if (r>=4){
        int i=r-4;
#pragma unroll
        for (int g=0;g<4;++g) A[g]-=K2[i][g];
        float s4=K2[i][0]+K2[i][1], s5=s4+K2[i][2]+K2[i][3];
        A[4]-=s4; A[5]-=s5;
        C[4]=C2m[i][0]; C[5]=C2m[i][1];
    }
    if (r<4){
#pragma unroll
        for (int d=0;d<4;++d) J[d]=Si[r][d];
        J[4]=Si[r][0]+Si[r][1]; J[5]=J[4]+Si[r][2]+Si[r][3];
    } else {
#pragma unroll
        for (int d=0;d<6;++d){
            float v0=(d<4)?Si[0][d]:((d==4)?Si[0][0]+Si[0][1]:Si[0][0]+Si[0][1]+Si[0][2]+Si[0][3]);
            float v1=(d<4)?Si[1][d]:((d==4)?Si[1][0]+Si[1][1]:Si[1][0]+Si[1][1]+Si[1][2]+Si[1][3]);
            float v2=(d<4)?Si[2][d]:((d==4)?Si[2][0]+Si[2][1]:Si[2][0]+Si[2][1]+Si[2][2]+Si[2][3]);
            float v3=(d<4)?Si[3][d]:((d==4)?Si[3][0]+Si[3][1]:Si[3][0]+Si[3][1]+Si[3][2]+Si[3][3]);
            J[d]=(r==4)?(v0+v1):(v0+v1+v2+v3);
        }
    }
#pragma unroll
    for (int i=0;i<6;++i) b[i]=0.0f;
#pragma unroll
    for (int i=0;i<2;++i){
        float s=0.0f;
#pragma unroll
        for (int g=0;g<4;++g) s+=K2[i][g]*yb[g];
        b[4+i]=s;
    }
    float u[4];
#pragma unroll
    for (int g=0;g<4;++g){ float s=0.0f;
#pragma unroll
        for (int h=0;h<4;++h) s+=Si[g][h]*yb[h]; u[g]=s; }
    e[0]=u[0]; e[1]=u[1]; e[2]=u[2]; e[3]=u[3];
    e[4]=u[0]+u[1]; e[5]=u[0]+u[1]+u[2]+u[3];
}

// ---- Phase A: 52 active blocks (1 warp each, 5 chunks/warp), 8 serial composes
__global__ void __launch_bounds__(32) phaseA(
    const float* __restrict__ track, const float* __restrict__ bs,
    const float* __restrict__ onp, const float* __restrict__ tnp)
{
    int lane = threadIdx.x;
    if (lane >= 30) return;
    int g = lane/6, r = lane - g*6, base = g*6;
    unsigned mask = 0x3Fu << base;
    int chunk = blockIdx.x*5 + g;
    if (chunk >= NCH) return;

    const float sig2 = onp[0]*onp[0];
    const float q = tnp[0]*tnp[0];
    const float rn = sig2/32.0f;
    float Qs[2][2] = {{q/3.0f, q*0.5f},{q*0.5f, q}};
    float S4[4][4], Si[4][4];
#pragma unroll
    for (int gg=0;gg<4;++gg)
#pragma unroll
        for (int h=0;h<4;++h) S4[gg][h]=Qs[gg>>1][h>>1]+((gg==h)?rn:0.0f);
    inv4f(S4,Si);
    float K2[2][4];
#pragma unroll
    for (int i=0;i<2;++i)
#pragma unroll
        for (int gg=0;gg<4;++gg){ float s=0.0f;
#pragma unroll
            for (int h=0;h<4;++h) s+=Qs[i][h>>1]*Si[h][gg]; K2[i][gg]=s; }
    float C2m[2][2];
#pragma unroll
    for (int i=0;i<2;++i)
#pragma unroll
        for (int j=0;j<2;++j){ float s=Qs[i][j];
#pragma unroll
            for (int gg=0;gg<4;++gg) s-=K2[i][gg]*Qs[gg>>1][j]; C2m[i][j]=s; }
    { float m=0.5f*(C2m[0][1]+C2m[1][0]); C2m[0][1]=m; C2m[1][0]=m; }

    float Ar[6],Cr[6],Jr[6],br[6],er[6];
    int idx0 = chunk*CHSZ;
    if (chunk == 0) {
        float P[6][6];
#pragma unroll
        for (int x=0;x<6;++x)
#pragma unroll
            for (int c=0;c<6;++c) P[x][c]=0.0f;
        P[0][0]=bs[0]/32.0f; P[1][1]=bs[1]/32.0f;
        P[2][2]=P[0][0]; P[3][3]=P[1][1];
        P[4][4]=2.0f+Qs[0][0]; P[4][5]=1.0f+Qs[0][1];
        P[5][4]=1.0f+Qs[0][1]; P[5][5]=1.0f+Qs[1][1];
        float PH[6][4];
#pragma unroll
        for (int x=0;x<6;++x)
#pragma unroll
            for (int gg=0;gg<4;++gg) PH[x][gg]=P[x][gg]+P[x][4+(gg>>1)];
        float S4f[4][4], Sif[4][4];
#pragma unroll
        for (int gg=0;gg<4;++gg)
#pragma unroll
            for (int h=0;h<4;++h) S4f[gg][h]=PH[gg][h]+PH[4+(gg>>1)][h]+((gg==h)?rn:0.0f);
        inv4f(S4f,Sif);
        float K[6][4];
#pragma unroll
        for (int x=0;x<6;++x)
#pragma unroll
            for (int gg=0;gg<4;++gg){ float s=0.0f;
#pragma unroll
                for (int h=0;h<4;++h) s+=PH[x][h]*Sif[h][gg]; K[x][gg]=s; }
        float y0=track[0], y1=track[1];
        float yb[4]={y0,y1,y0,y1};
#pragma unroll
        for (int x=0;x<6;++x){ float s=0.0f;
#pragma unroll
            for (int gg=0;gg<4;++gg) s+=K[x][gg]*yb[gg]; br[x]=s; }
        float Cf[6][6];
#pragma unroll
        for (int x=0;x<6;++x)
#pragma unroll
            for (int c=0;c<6;++c){ float s=P[x][c];
#pragma unroll
                for (int gg=0;gg<4;++gg) s-=K[x][gg]*PH[c][gg]; Cf[x][c]=s; }
#pragma unroll
        for (int x=0;x<6;++x)
#pragma unroll
            for (int c=x+1;c<6;++c){ float m=0.5f*(Cf[x][c]+Cf[c][x]); Cf[x][c]=m; Cf[c][x]=m; }
#pragma unroll
        for (int c=0;c<6;++c){ Ar[c]=0.0f; Jr[c]=0.0f; er[c]=0.0f; Cr[c]=Cf[r][c]; }
    } else {
        build_step(r, track[2*idx0], track[2*idx0+1], Si, K2, C2m, Ar,Cr,Jr,br,er);
    }
    float* dst = &g_loc[idx0*ESTR];
#pragma unroll
    for (int k=0;k<6;++k){ dst[oA+r*6+k]=Ar[k]; dst[oC+r*6+k]=Cr[k]; dst[oJ+r*6+k]=Jr[k]; }
    if (r==0){
#pragma unroll
        for (int k=0;k<6;++k){ dst[oB+k]=br[k]; dst[oE+k]=er[k]; }
    }
    for (int k=1;k<CHSZ;++k){
        int idx=idx0+k;
        float A2[6],C2[6],J2[6],b2[6],e2[6];
        build_step(r, track[2*idx], track[2*idx+1], Si, K2, C2m, A2,C2,J2,b2,e2);
        float Ao[6],Co[6],Jo[6],bo[6],eo[6];
        compose_rp<float,true>(mask,base,r,Ar,Cr,Jr,br,er,A2,C2,J2,b2,e2,Ao,Co,Jo,bo,eo);
#pragma unroll
        for (int j=0;j<6;++j){ Ar[j]=Ao[j]; Cr[j]=Co[j]; Jr[j]=Jo[j]; br[j]=bo[j]; er[j]=eo[j]; }
        float* d2 = &g_loc[idx*ESTR];
#pragma unroll
        for (int j=0;j<6;++j){ d2[oA+r*6+j]=Ar[j]; d2[oC+r*6+j]=Cr[j]; d2[oJ+r*6+j]=Jr[j]; }
        if (r==0){
#pragma unroll
            for (int j=0;j<6;++j){ d2[oB+j]=br[j]; d2[oE+j]=er[j]; }
        }
    }
    float* ag = &g_agg[0][chunk*ESTR];
#pragma unroll
    for (int j=0;j<6;++j){ ag[oA+r*6+j]=Ar[j]; ag[oC+r*6+j]=Cr[j]; ag[oJ+r*6+j]=Jr[j]; }
    if (r==0){
#pragma unroll
        for (int j=0;j<6;++j){ ag[oB+j]=br[j]; ag[oE+j]=er[j]; }
    }
}

// ---- Phase B: single working block, Kogge-Stone over 256 aggregates
__global__ void __launch_bounds__(512) phaseB() {
    if (blockIdx.x != 0) return;
    int lane = threadIdx.x & 31, warp = threadIdx.x >> 5;
    int g = lane/6, r = lane - g*6, base = g*6;
    bool act = (lane < 30);
    unsigned mask = 0x3Fu << base;
    int grp = warp*5 + g;
    int p = 0;
    for (int d=1; d<NCH; d<<=1) {
        for (int it=0; it<4; ++it) {
            int gid = grp + it*80;
            if (act && gid < NCH) {
                const float* src = g_agg[p];
                float* dst = g_agg[p^1];
                const float* ej = &src[gid*ESTR];
                float* dd = &dst[gid*ESTR];
                if (gid < d) {
#pragma unroll
                    for (int j=0;j<20;++j) dd[r*20+j]=ej[r*20+j];
                } else {
                    const float* ei = &src[(gid-d)*ESTR];
                    float A1[6],C1[6],J1[6],b1[6],e1[6],A2[6],C2[6],J2[6],b2[6],e2[6];
#pragma unroll
                    for (int k=0;k<6;++k){
                        A1[k]=ei[oA+r*6+k]; C1[k]=ei[oC+r*6+k]; J1[k]=ei[oJ+r*6+k];
                        A2[k]=ej[oA+r*6+k]; C2[k]=ej[oC+r*6+k]; J2[k]=ej[oJ+r*6+k];
                        b1[k]=ei[oB+k]; e1[k]=ei[oE+k]; b2[k]=ej[oB+k]; e2[k]=ej[oE+k];
                    }
                    float Ao[6],Co[6],Jo[6],bo[6],eo[6];
                    compose_rp<float,true>(mask,base,r,A1,C1,J1,b1,e1,A2,C2,J2,b2,e2,Ao,Co,Jo,bo,eo);
#pragma unroll
                    for (int k=0;k<6;++k){ dd[oA+r*6+k]=Ao[k]; dd[oC+r*6+k]=Co[k]; dd[oJ+r*6+k]=Jo[k]; }
                    if (r==0){
#pragma unroll
                        for (int k=0;k<6;++k){ dd[oB+k]=bo[k]; dd[oE+k]=eo[k]; }
                    }
                }
            }
        }
        __syncthreads();
        p ^= 1;
    }
}

// ---- Phase C: 148 blocks, interleaved warps; per-step prefix + fp64 ll term
__global__ void __launch_bounds__(256) phaseC(
    const float* __restrict__ track, const float* __restrict__ bs,
    const float* __restrict__ onp, const float* __restrict__ tnp)
{
    int lane = threadIdx.x & 31, warp = threadIdx.x >> 5;
    int g = lane/6, r = lane - g*6, base = g*6;
    bool act = (lane < 30);
    unsigned mask = 0x3Fu << base;
    int t = (warp*148 + blockIdx.x)*5 + g;
    const double sig2 = (double)onp[0]*(double)onp[0];
    const double q = (double)tnp[0]*(double)tnp[0];
    const double rn = sig2/32.0;
    double llt = 0.0;
    if (act && t < TS) {
        double m[6], P[6][6];
        if (t == 0) {
            if (r==0) {
                for (int i=0;i<6;++i) m[i]=0.0;
                for (int x=0;x<6;++x) for (int c=0;c<6;++c) P[x][c]=0.0;
                P[0][0]=(double)bs[0]/32.0; P[1][1]=(double)bs[1]/32.0;
                P[2][2]=P[0][0]; P[3][3]=P[1][1]; P[4][4]=1.0; P[5][5]=1.0;
            }
        } else {
            int s = t-1, c = s>>3;
            float Crow[6], bv[6];
            if (c == 0) {
                const float* e = &g_loc[s*ESTR];
#pragma unroll
                for (int k=0;k<6;++k){ Crow[k]=e[oC+r*6+k]; bv[k]=e[oB+k]; }
            } else {
                const float* ei = &g_agg[0][(c-1)*ESTR];
                const float* ej = &g_loc[s*ESTR];
                float A1[6],C1[6],J1[6],b1[6],e1[6],A2[6],C2[6],J2[6],b2[6],e2[6];
#pragma unroll
                for (int k=0;k<6;++k){
                    A1[k]=ei[oA+r*6+k]; C1[k]=ei[oC+r*6+k]; J1[k]=ei[oJ+r*6+k];
                    A2[k]=ej[oA+r*6+k]; C2[k]=ej[oC+r*6+k]; J2[k]=ej[oJ+r*6+k];
                    b1[k]=ei[oB+k]; e1[k]=ei[oE+k]; b2[k]=ej[oB+k]; e2[k]=ej[oE+k];
                }
                float Ao[6],Co[6],Jo[6],bo[6],eo[6];
                compose_rp<float,true>(mask,base,r,A1,C1,J1,b1,e1,A2,C2,J2,b2,e2,Ao,Co,Jo,bo,eo);
#pragma unroll
                for (int k=0;k<6;++k){ Crow[k]=Co[k]; bv[k]=bo[k]; }
            }
            float Pf[6][6];
#pragma unroll
            for (int rr=0;rr<6;++rr)
#pragma unroll
                for (int k=0;k<6;++k) Pf[rr][k]=__shfl_sync(mask, Crow[k], base+rr);
            if (r==0) {
                for (int i=0;i<6;++i) m[i]=(double)bv[i];
                for (int x=0;x<6;++x) for (int cc=0;cc<6;++cc) P[x][cc]=(double)Pf[x][cc];
            }
        }
        if (r==0) {
            double mp[6];
            for (int i=0;i<4;++i) mp[i]=m[i];
            mp[4]=m[4]+m[5]; mp[5]=m[5];
            for (int c=0;c<6;++c) P[4][c]+=P[5][c];
            for (int x=0;x<6;++x) P[x][4]+=P[x][5];
            P[4][4]+=q/3.0; P[4][5]+=q*0.5; P[5][4]+=q*0.5; P[5][5]+=q;
            double y0=(double)track[2*t], y1=(double)track[2*t+1];
            double yb[4]={y0,y1,y0,y1};
            double S4[4][4], v[4];
            for (int gg=0;gg<4;++gg){
                int rg=gg>>1;
                v[gg]=yb[gg]-(mp[gg]+mp[4+rg]);
                for (int h=0;h<4;++h){
                    int rh=h>>1;
                    S4[gg][h]=P[gg][h]+P[gg][4+rh]+P[4+rg][h]+P[4+rg][4+rh]+((gg==h)?rn:0.0);
                }
            }
            double Sid[4][4];
            double det=inv4d(S4,Sid);
            double quad=0.0;
            for (int gg=0;gg<4;++gg) for (int h=0;h<4;++h) quad+=v[gg]*Sid[gg][h]*v[h];
            double tf=(double)t;
            double d0=1.0/(1.0/(double)bs[0]+tf/sig2)+sig2;
            double d1=1.0/(1.0/(double)bs[1]+tf/sig2)+sig2;
            double step=128.0*LOG2PI + 62.0*(log(d0)+log(d1))
                      + 4.0*log(32.0) + log(det) + quad;
            llt = -0.5*step;
        }
    }
    __shared__ double sd[256];
    sd[threadIdx.x] = (act && r==0 && t<TS) ? llt : 0.0;
    __syncthreads();
    for (int s=128;s>0;s>>=1){
        if ((int)threadIdx.x < s) sd[threadIdx.x]+=sd[threadIdx.x+s];
        __syncthreads();
    }
    if (threadIdx.x==0) g_llp[blockIdx.x]=sd[0];
}

// ---- Finalize (148 x 128): every block redundantly does the fp64 binary
// powering in shared memory, thread 0 does assembly, block fills its slice.
__global__ void __launch_bounds__(128)
finalize(const float* __restrict__ bs, const float* __restrict__ onp,
         const float* __restrict__ tnp,
         float* __restrict__ out, int out_size, int nblk) {
    __shared__ double sp[108], sr[108], sP6[36];
    __shared__ double sLam4[4], sPhi[4][4], sE[4][2], sSsInv[2][2], sPu[3];
    __shared__ double sll;
    int lane = threadIdx.x & 31;
    int w = threadIdx.x >> 5;
    const unsigned mask = 0x3Fu;
    const double sig2 = (double)onp[0]*(double)onp[0];
    const double q = (double)tnp[0]*(double)tnp[0];
    const double rn = sig2/32.0;
    double Qs[2][2]={{q/3.0,q*0.5},{q*0.5,q}};
    if (w==0 && lane<6) {
        int r=lane;
        double S4[4][4],Si[4][4];
        for (int gg=0;gg<4;++gg) for (int h=0;h<4;++h)
            S4[gg][h]=Qs[gg>>1][h>>1]+((gg==h)?rn:0.0);
        inv4d(S4,Si);
        double K2[2][4];
        for (int i=0;i<2;++i) for (int gg=0;gg<4;++gg){
            double s=0; for (int h=0;h<4;++h) s+=Qs[i][h>>1]*Si[h][gg]; K2[i][gg]=s; }
        double Ar[6];
#pragma unroll
        for (int c=0;c<6;++c) Ar[c]=(r==c)?1.0:0.0;
        if (r==4) Ar[5]=1.0;
        if (r>=4){
            int i=r-4;
            for (int gg=0; gg<4; ++gg) Ar[gg]-=K2[i][gg];
            double s4=K2[i][0]+K2[i][1], s5=s4+K2[i][2]+K2[i][3];
            Ar[4]-=s4; Ar[5]-=s5;
        }
        double C2m[2][2];
        for (int i=0;i<2;++i) for (int j=0;j<2;++j){
            double s=Qs[i][j];
            for (int gg=0;gg<4;++gg) s-=K2[i][gg]*Qs[gg>>1][j];
            C2m[i][j]=s;
        }
        { double m=0.5*(C2m[0][1]+C2m[1][0]); C2m[0][1]=m; C2m[1][0]=m; }
        double Cr[6]={0,0,0,0,0,0};
        if (r>=4){ Cr[4]=C2m[r-4][0]; Cr[5]=C2m[r-4][1]; }
        double V[4][6];
        for (int gg=0;gg<4;++gg){
            for (int d=0;d<4;++d) V[gg][d]=Si[gg][d];
            V[gg][4]=Si[gg][0]+Si[gg][1];
            V[gg][5]=V[gg][4]+Si[gg][2]+Si[gg][3];
        }
        double Jr[6];
#pragma unroll
        for (int c=0;c<6;++c){
            double s=0;
            for (int gg=0; gg<4; ++gg) if (r==gg) s=V[gg][c];
            if (r==4) s=V[0][c]+V[1][c];
            if (r==5) s=V[0][c]+V[1][c]+V[2][c]+V[3][c];
            Jr[c]=s;
        }
#pragma unroll
        for (int c=0;c<6;++c){
            sp[r*6+c]=Ar[c]; sp[36+r*6+c]=Cr[c]; sp[72+r*6+c]=Jr[c];
            sr[r*6+c]=(r==c)?1.0:0.0; sr[36+r*6+c]=0.0; sr[72+r*6+c]=0.0;
        }
    }
    __syncthreads();
    double dm[6];
    for (int it=0; it<11; ++it) {
        double A1[6],C1[6],J1[6],A2[6],C2[6],J2[6],Ao[6],Co[6],Jo[6];
        if (w<2 && lane<6) {
            int r=lane;
            const double* eb = (w==0)? sp : sr;
#pragma unroll
            for (int k=0;k<6;++k){
                A1[k]=eb[r*6+k]; C1[k]=eb[36+r*6+k]; J1[k]=eb[72+r*6+k];
                A2[k]=sp[r*6+k]; C2[k]=sp[36+r*6+k]; J2[k]=sp[72+r*6+k];
            }
        }
        __syncthreads();
        if (w<2 && lane<6) {
            int r=lane;
            compose_rp<double,false>(mask,0,r,A1,C1,J1,dm,dm,A2,C2,J2,dm,dm,Ao,Co,Jo,dm,dm);
            double* ob = (w==0)? sp : sr;
#pragma unroll
            for (int k=0;k<6;++k){ ob[r*6+k]=Ao[k]; ob[36+r*6+k]=Co[k]; ob[72+r*6+k]=Jo[k]; }
        }
        __syncthreads();
    }
    if (w==0 && lane<6) {
        int r=lane;
        double P[36];
#pragma unroll
        for (int i=0;i<36;++i) P[i]=0.0;
        P[0]=(double)bs[0]/32.0; P[7]=(double)bs[1]/32.0;
        P[14]=P[0]; P[21]=P[7];
        P[4*6+4]=2.0+Qs[0][0]; P[4*6+5]=1.0+Qs[0][1];
        P[5*6+4]=1.0+Qs[0][1]; P[5*6+5]=1.0+Qs[1][1];
        double PH[24];
        for (int x=0;x<6;++x) for (int gg=0;gg<4;++gg) PH[x*4+gg]=P[x*6+gg]+P[x*6+4+(gg>>1)];
        double S4f[4][4], Sif[4][4];
        for (int gg=0;gg<4;++gg) for (int h=0;h<4;++h)
            S4f[gg][h]=PH[gg*4+h]+PH[(4+(gg>>1))*4+h]+((gg==h)?rn:0.0);
        inv4d(S4f,Sif);
        double Kr[4];
        for (int gg=0;gg<4;++gg){ double s=0;
            for (int h=0;h<4;++h) s+=PH[r*4+h]*Sif[h][gg]; Kr[gg]=s; }
        double A1[6],C1[6],J1[6],A2[6],C2[6],J2[6],Ao[6],Co[6],Jo[6];
#pragma unroll
        for (int c=0;c<6;++c){
            double s=P[r*6+c];
            for (int gg=0;gg<4;++gg) s-=Kr[gg]*PH[c*4+gg];
            C1[c]=s; A1[c]=0.0; J1[c]=0.0;
            A2[c]=sr[r*6+c]; C2[c]=sr[36+r*6+c]; J2[c]=sr[72+r*6+c];
        }
        compose_rp<double,false>(mask,0,r,A1,C1,J1,dm,dm,A2,C2,J2,dm,dm,Ao,Co,Jo,dm,dm);
#pragma unroll
        for (int c=0;c<6;++c) sP6[r*6+c]=Co[c];
    }
    __syncthreads();
    if (threadIdx.x == 0) {
        double ll=0.0;
        for (int i=0;i<nblk;++i) ll+=g_llp[i];
        sll=ll;
        double P6[6][6];
        for (int r=0;r<6;++r) for (int c=0;c<6;++c) P6[r][c]=sP6[r*6+c];
        double aT0=1.0/(1.0/(double)bs[0]+2048.0/sig2);
        double aT1=1.0/(1.0/(double)bs[1]+2048.0/sig2);
        double a[4]={aT0,aT1,aT0,aT1};
        double B[4][4], C[4][2];
        for (int gg=0;gg<4;++gg){
            for (int h=0;h<4;++h) B[gg][h]=P6[gg][h]-((gg==h)?a[gg]/32.0:0.0);
            C[gg][0]=P6[gg][4]; C[gg][1]=P6[gg][5];
        }
        double p00=P6[4][4], p02=P6[4][5], p22=P6[5][5];
        double La[4]={1.0/a[0],1.0/a[1],1.0/a[2],1.0/a[3]};
        double Xb[4][4];
        for (int gg=0;gg<4;++gg) for (int h=0;h<4;++h)
            Xb[gg][h]=((gg==h)?1.0:0.0)+32.0*La[gg]*B[gg][h];
        double Yb[4][4]; inv4d(Xb,Yb);
        double G[4][4];
        for (int gg=0;gg<4;++gg) for (int h=0;h<4;++h){
            double s=0; for (int k=0;k<4;++k) s+=B[gg][k]*Yb[k][h];
            G[gg][h]=La[gg]*s*La[h];
        }
        double M4[4][4];
        for (int gg=0;gg<4;++gg) for (int h=0;h<4;++h)
            M4[gg][h]=((gg==h)?La[gg]:0.0)-32.0*G[gg][h];
        double MC[4][2];
        for (int gg=0;gg<4;++gg){
            double t0=0,t1=0;
            for (int k=0;k<4;++k){ t0+=M4[gg][k]*C[k][0]; t1+=M4[gg][k]*C[k][1]; }
            MC[gg][0]=t0; MC[gg][1]=t1;
        }
        double ss00=p00, ss01=p02, ss11=p22;
        for (int gg=0;gg<4;++gg){
            ss00-=32.0*C[gg][0]*MC[gg][0];
            ss01-=32.0*C[gg][0]*MC[gg][1];
            ss11-=32.0*C[gg][1]*MC[gg][1];
        }
        {
            double det=ss00*ss11-ss01*ss01;
            double id=1.0/det;
            sSsInv[0][0]=ss11*id; sSsInv[0][1]=-ss01*id;
            sSsInv[1][0]=-ss01*id; sSsInv[1][1]=ss00*id;
        }
        for (int gg=0;gg<4;++gg){
            sE[gg][0]=-(MC[gg][0]*sSsInv[0][0]+MC[gg][1]*sSsInv[1][0]);
            sE[gg][1]=-(MC[gg][0]*sSsInv[0][1]+MC[gg][1]*sSsInv[1][1]);
        }
        for (int gg=0;gg<4;++gg) for (int h=0;h<4;++h)
            sPhi[gg][h]=-G[gg][h]-(sE[gg][0]*MC[h][0]+sE[gg][1]*MC[h][1]);
        for (int gg=0;gg<4;++gg) sLam4[gg]=La[gg];
        {
            const double td=2048.0;
            double sum00=td/3.0+td*(td-1.0)/2.0+(td-1.0)*td*(2.0*td-1.0)/6.0;
            double sum01=td/2.0+td*(td-1.0)/2.0;
            double pu00=1.0+td*td+q*sum00;
            double pu01=td+q*sum01;
            double pu11=1.0+q*td;
            double det=pu00*pu11-pu01*pu01, idd=1.0/det;
            sPu[0]=pu11*idd; sPu[1]=-pu01*idd; sPu[2]=pu00*idd;
        }
    }
    __syncthreads();
    const int off = (out_size >= 17425) ? 1 : 0;
    if (blockIdx.x == 0 && threadIdx.x == 0 && off) out[0] = (float)sll;
    int ecnt = blockIdx.x*128 + threadIdx.x;
    if (ecnt < 17424) {
        int r = ecnt / 132, c = ecnt % 132;
        double val = 0.0;
        if (r < 128 && c < 128) {
            int gg=(r&1)+((r>=64)?2:0), h=(c&1)+((c>=64)?2:0);
            val=sPhi[gg][h];
            if (r==c) val+=sLam4[gg];
        } else if (r < 128) {
            int gg=(r&1)+((r>=64)?2:0), j=c-128;
            if (j==0) val=sE[gg][0]; else if (j==2) val=sE[gg][1];
        } else if (c < 128) {
            int h=(c&1)+((c>=64)?2:0), i=r-128;
            if (i==0) val=sE[h][0]; else if (i==2) val=sE[h][1];
        } else {
            int i=r-128, j=c-128;
            if ((i==0||i==2)&&(j==0||j==2)) val=sSsInv[i>>1][j>>1];
            else if (i==1&&j==1) val=sPu[0];
            else if ((i==1&&j==3)||(i==3&&j==1)) val=sPu[1];
            else if (i==3&&j==3) val=sPu[2];
        }
        out[off+ecnt]=(float)val;
    }
}

extern "C" void kernel_launch(void* const* d_in, const int* in_sizes, int n_in,
                              void* d_out, int out_size) {
    const float* track       = (const float*)d_in[0];
    const float* bias_scales = (const float*)d_in[1];
    const float* obs_noise   = (const float*)d_in[2];
    const float* trans_noise = (const float*)d_in[3];
    float* out = (float*)d_out;
    phaseA<<<148,32>>>(track, bias_scales, obs_noise, trans_noise);
    phaseB<<<148,512>>>();
    phaseC<<<148,256>>>(track, bias_scales, obs_noise, trans_noise);
    finalize<<<148,128>>>(bias_scales, obs_noise, trans_noise, out, out_size, 148);
}

// round 15
// speedup vs baseline: 2.8959x; 2.8959x over previous
#include <cuda_runtime.h>
#include <math.h>

#define TS 2048
#define ESTR 128
#define oA 0
#define oB 36
#define oC 42
#define oE 78
#define oJ 84
#define LOG2PI 1.8378770664093454836

__device__ float g_buf[2][TS*ESTR];
__device__ double g_llp[16];
__device__ double g_P6[36];

template<typename T> __device__ __forceinline__ T tabs(T x){ return x < T(0) ? -x : x; }

__device__ __forceinline__ float inv4f(const float A[4][4], float R[4][4]) {
    float a00=A[0][0],a01=A[0][1],a02=A[0][2],a03=A[0][3];
    float a10=A[1][0],a11=A[1][1],a12=A[1][2],a13=A[1][3];
    float a20=A[2][0],a21=A[2][1],a22=A[2][2],a23=A[2][3];
    float a30=A[3][0],a31=A[3][1],a32=A[3][2],a33=A[3][3];
    float s0=a00*a11-a10*a01,s1=a00*a12-a10*a02,s2=a00*a13-a10*a03;
    float s3=a01*a12-a11*a02,s4=a01*a13-a11*a03,s5=a02*a13-a12*a03;
    float c5=a22*a33-a32*a23,c4=a21*a33-a31*a23,c3=a21*a32-a31*a22;
    float c2=a20*a33-a30*a23,c1=a20*a32-a30*a22,c0=a20*a31-a30*a21;
    float det=s0*c5-s1*c4+s2*c3+s3*c2-s4*c1+s5*c0;
    float id=__fdividef(1.0f,det);
    R[0][0]=( a11*c5-a12*c4+a13*c3)*id; R[0][1]=(-a01*c5+a02*c4-a03*c3)*id;
    R[0][2]=( a31*s5-a32*s4+a33*s3)*id; R[0][3]=(-a21*s5+a22*s4-a23*s3)*id;
    R[1][0]=(-a10*c5+a12*c2-a13*c1)*id; R[1][1]=( a00*c5-a02*c2+a03*c1)*id;
    R[1][2]=(-a30*s5+a32*s2-a33*s1)*id; R[1][3]=( a20*s5-a22*s2+a23*s1)*id;
    R[2][0]=( a10*c4-a11*c2+a13*c0)*id; R[2][1]=(-a00*c4+a01*c2-a03*c0)*id;
    R[2][2]=( a30*s4-a31*s2+a33*s0)*id; R[2][3]=(-a20*s4+a21*s2-a23*s0)*id;
    R[3][0]=(-a10*c3+a11*c1-a12*c0)*id; R[3][1]=( a00*c3-a01*c1+a02*c0)*id;
    R[3][2]=(-a30*s3+a31*s1-a32*s0)*id; R[3][3]=( a20*s3-a21*s1+a22*s0)*id;
    return det;
}

__device__ __forceinline__ double inv4d(const double A[4][4], double R[4][4]) {
    double a00=A[0][0],a01=A[0][1],a02=A[0][2],a03=A[0][3];
    double a10=A[1][0],a11=A[1][1],a12=A[1][2],a13=A[1][3];
    double a20=A[2][0],a21=A[2][1],a22=A[2][2],a23=A[2][3];
    double a30=A[3][0],a31=A[3][1],a32=A[3][2],a33=A[3][3];
    double s0=a00*a11-a10*a01,s1=a00*a12-a10*a02,s2=a00*a13-a10*a03;
    double s3=a01*a12-a11*a02,s4=a01*a13-a11*a03,s5=a02*a13-a12*a03;
    double c5=a22*a33-a32*a23,c4=a21*a33-a31*a23,c3=a21*a32-a31*a22;
    double c2=a20*a33-a30*a23,c1=a20*a32-a30*a22,c0=a20*a31-a30*a21;
    double det=s0*c5-s1*c4+s2*c3+s3*c2-s4*c1+s5*c0;
    double id=1.0/det;
    R[0][0]=( a11*c5-a12*c4+a13*c3)*id; R[0][1]=(-a01*c5+a02*c4-a03*c3)*id;
    R[0][2]=( a31*s5-a32*s4+a33*s3)*id; R[0][3]=(-a21*s5+a22*s4-a23*s3)*id;
    R[1][0]=(-a10*c5+a12*c2-a13*c1)*id; R[1][1]=( a00*c5-a02*c2+a03*c1)*id;
    R[1][2]=(-a30*s5+a32*s2-a33*s1)*id; R[1][3]=( a20*s5-a22*s2+a23*s1)*id;
    R[2][0]=( a10*c4-a11*c2+a13*c0)*id; R[2][1]=(-a00*c4+a01*c2-a03*c0)*id;
    R[2][2]=( a30*s4-a31*s2+a33*s0)*id; R[2][3]=(-a20*s4+a21*s2-a23*s0)*id;
    R[3][0]=(-a10*c3+a11*c1-a12*c0)*id; R[3][1]=( a00*c3-a01*c1+a02*c0)*id;
    R[3][2]=(-a30*s3+a31*s1-a32*s0)*id; R[3][3]=( a20*s3-a21*s1+a22*s0)*id;
    return det;
}

// Row-parallel Sarkka composition (round-10 version).
template<typename T, bool VEC>
__device__ __forceinline__ void compose_rp(
    unsigned mask, int base, int r,
    const T* A1, const T* C1, const T* J1, const T* b1, const T* e1,
    const T* A2, const T* C2, const T* J2, const T* b2, const T* e2,
    T* Ao, T* Co, T* Jo, T* bo, T* eo)
{
    T M[12];
#pragma unroll
    for (int c=0;c<6;++c){
        T s=(r==c)?T(1):T(0);
#pragma unroll
        for (int k=0;k<6;++k) s += C1[k]*__shfl_sync(mask, J2[c], base+k);
        M[c]=s; M[6+c]=(r==c)?T(1):T(0);
    }
#pragma unroll
    for (int col=0;col<6;++col){
        T v = (r>=col)?tabs(M[col]):T(-1);
        int p=col; T bv=__shfl_sync(mask, v, base+col);
#pragma unroll
        for (int rr=0;rr<6;++rr){
            T vv=__shfl_sync(mask, v, base+rr);
            if (rr>col && vv>bv){ bv=vv; p=rr; }
        }
        int src = (r==col)?p:((r==p)?col:r);
#pragma unroll
        for (int j=0;j<12;++j) M[j]=__shfl_sync(mask, M[j], base+src);
        T piv=__shfl_sync(mask, M[col], base+col);
        T ip=T(1)/piv;
        if (r==col){
#pragma unroll
            for (int j=0;j<12;++j) M[j]*=ip;
        }
        T f=M[col];
        T pr[12];
#pragma unroll
        for (int j=0;j<12;++j) pr[j]=__shfl_sync(mask, M[j], base+col);
        if (r!=col){
#pragma unroll
            for (int j=0;j<12;++j) M[j]-=f*pr[j];
        }
    }
    T D[6];
#pragma unroll
    for (int c=0;c<6;++c) D[c]=M[6+c];
    T T1[6];
#pragma unroll
    for (int c=0;c<6;++c){ T s=T(0);
#pragma unroll
        for (int k=0;k<6;++k) s+=D[k]*__shfl_sync(mask, A1[c], base+k);
        T1[c]=s; }
#pragma unroll
    for (int c=0;c<6;++c){ T s=T(0);
#pragma unroll
        for (int k=0;k<6;++k) s+=A2[k]*__shfl_sync(mask, T1[c], base+k);
        Ao[c]=s; }
    if (VEC) {
        T u[6], wv[6];
#pragma unroll
        for (int i=0;i<6;++i){ T s=b1[i];
#pragma unroll
            for (int k=0;k<6;++k) s+=__shfl_sync(mask, C1[k], base+i)*e2[k];
            u[i]=s; }
#pragma unroll
        for (int i=0;i<6;++i){ T s=T(0);
#pragma unroll
            for (int k=0;k<6;++k) s+=__shfl_sync(mask, D[k], base+i)*u[k];
            wv[i]=s; }
#pragma unroll
        for (int i=0;i<6;++i){ T s=b2[i];
#pragma unroll
            for (int k=0;k<6;++k) s+=__shfl_sync(mask, A2[k], base+i)*wv[k];
            bo[i]=s; }
        T rv[6];
#pragma unroll
        for (int k=0;k<6;++k){ T s=e2[k];
#pragma unroll
            for (int m=0;m<6;++m) s-=__shfl_sync(mask, J2[m], base+k)*b1[m];
            rv[k]=s; }
#pragma unroll
        for (int c=0;c<6;++c){ T s=e1[c];
#pragma unroll
            for (int k=0;k<6;++k) s+=__shfl_sync(mask, T1[c], base+k)*rv[k];
            eo[c]=s; }
    }
    T S[6], Tt[6];
#pragma unroll
    for (int c=0;c<6;++c){ T s=T(0);
#pragma unroll
        for (int k=0;k<6;++k) s+=D[k]*__shfl_sync(mask, C1[c], base+k);
        S[c]=s; }
#pragma unroll
    for (int c=0;c<6;++c){ T s=T(0);
#pragma unroll
        for (int k=0;k<6;++k) s+=A2[k]*__shfl_sync(mask, S[c], base+k);
        Tt[c]=s; }
#pragma unroll
    for (int c=0;c<6;++c){ T s=C2[c];
#pragma unroll
        for (int k=0;k<6;++k) s+=Tt[k]*__shfl_sync(mask, A2[k], base+c);
        Co[c]=s; }
    T T5[6];
#pragma unroll
    for (int c=0;c<6;++c){ T s=T(0);
#pragma unroll
        for (int k=0;k<6;++k) s+=J2[k]*__shfl_sync(mask, A1[c], base+k);
        T5[c]=s; }
    T T1t[6];
#pragma unroll
    for (int j=0;j<6;++j){
#pragma unroll
        for (int k=0;k<6;++k){
            T w2=__shfl_sync(mask, T1[j], base+k);
            if (r==j) T1t[k]=w2;
        }
    }
#pragma unroll
    for (int c=0;c<6;++c){ T s=J1[c];
#pragma unroll
        for (int k=0;k<6;++k) s+=T1t[k]*__shfl_sync(mask, T5[c], base+k);
        Jo[c]=s; }
}

__global__ void init_elems(const float* __restrict__ track, const float* __restrict__ bs,
                           const float* __restrict__ onp, const float* __restrict__ tnp) {
    int t = blockIdx.x*blockDim.x + threadIdx.x;
    if (t >= TS) return;
    float* e = &g_buf[0][t*ESTR];
    const float sig2 = onp[0]*onp[0];
    const float q = tnp[0]*tnp[0];
    const float rn = sig2/32.0f;
    float Qs[2][2] = {{q/3.0f, q*0.5f},{q*0.5f, q}};
    float y0 = track[2*t], y1 = track[2*t+1];
    float yb[4] = {y0,y1,y0,y1};
    if (t == 0) {
        float P[6][6];
        for (int r=0;r<6;++r) for (int c=0;c<6;++c) P[r][c]=0.0f;
        P[0][0]=bs[0]/32.0f; P[1][1]=bs[1]/32.0f;
        P[2][2]=P[0][0]; P[3][3]=P[1][1];
        P[4][4]=2.0f+Qs[0][0]; P[4][5]=1.0f+Qs[0][1];
        P[5][4]=1.0f+Qs[1][0]; P[5][5]=1.0f+Qs[1][1];
        float PH[6][4];
        for (int r=0;r<6;++r) for (int g=0;g<4;++g) PH[r][g]=P[r][g]+P[r][4+(g>>1)];
        float S4[4][4];
        for (int g=0;g<4;++g) for (int h=0;h<4;++h)
            S4[g][h]=PH[g][h]+PH[4+(g>>1)][h]+((g==h)?rn:0.0f);
        float Si[4][4]; inv4f(S4,Si);
        float K[6][4];
        for (int r=0;r<6;++r) for (int g=0;g<4;++g){
            float s=0; for (int h=0;h<4;++h) s+=PH[r][h]*Si[h][g]; K[r][g]=s; }
        for (int i=0;i<36;++i) e[oA+i]=0.0f;
        for (int r=0;r<6;++r){ float s=0; for (int g=0;g<4;++g) s+=K[r][g]*yb[g]; e[oB+r]=s; }
        for (int r=0;r<6;++r) for (int c=0;c<6;++c){
            float s=P[r][c]; for (int g=0;g<4;++g) s-=K[r][g]*PH[c][g];
            e[oC+r*6+c]=s;
        }
        for (int r=0;r<6;++r) for (int c=r+1;c<6;++c){
            float m=0.5f*(e[oC+r*6+c]+e[oC+c*6+r]); e[oC+r*6+c]=m; e[oC+c*6+r]=m; }
        for (int i=0;i<6;++i) e[oE+i]=0.0f;
        for (int i=0;i<36;++i) e[oJ+i]=0.0f;
    } else {
        float S4[4][4];
        for (int g=0;g<4;++g) for (int h=0;h<4;++h)
            S4[g][h]=Qs[g>>1][h>>1]+((g==h)?rn:0.0f);
        float Si[4][4]; inv4f(S4,Si);
        float K2[2][4];
        for (int i=0;i<2;++i) for (int g=0;g<4;++g){
            float s=0; for (int h=0;h<4;++h) s+=Qs[i][h>>1]*Si[h][g]; K2[i][g]=s; }
        float A[6][6];
        for (int r=0;r<6;++r) for (int c=0;c<6;++c) A[r][c]=(r==c)?1.0f:0.0f;
        A[4][5]=1.0f;
        for (int i=0;i<2;++i){
            for (int g=0;g<4;++g) A[4+i][g]-=K2[i][g];
            float s4=K2[i][0]+K2[i][1];
            float s5=s4+K2[i][2]+K2[i][3];
            A[4+i][4]-=s4; A[4+i][5]-=s5;
        }
        float C2[2][2];
        for (int i=0;i<2;++i) for (int j=0;j<2;++j){
            float s=Qs[i][j];
            for (int g=0;g<4;++g) s-=K2[i][g]*Qs[g>>1][j];
            C2[i][j]=s;
        }
        { float m=0.5f*(C2[0][1]+C2[1][0]); C2[0][1]=m; C2[1][0]=m; }
        for (int r=0;r<6;++r) e[oB+r]=0.0f;
        for (int i=0;i<2;++i){ float s=0; for (int g=0;g<4;++g) s+=K2[i][g]*yb[g]; e[oB+4+i]=s; }
        float u[4];
        for (int g=0;g<4;++g){ float s=0; for (int h=0;h<4;++h) s+=Si[g][h]*yb[h]; u[g]=s; }
        for (int c=0;c<4;++c) e[oE+c]=u[c];
        e[oE+4]=u[0]+u[1]; e[oE+5]=u[0]+u[1]+u[2]+u[3];
        float V[4][6];
        for (int g=0;g<4;++g){
            for (int d=0;d<4;++d) V[g][d]=Si[g][d];
            V[g][4]=Si[g][0]+Si[g][1];
            V[g][5]=Si[g][0]+Si[g][1]+Si[g][2]+Si[g][3];
        }
        float J[6][6];
        for (int c=0;c<4;++c) for (int d=0;d<6;++d) J[c][d]=V[c][d];
        for (int d=0;d<6;++d){ J[4][d]=V[0][d]+V[1][d]; J[5][d]=V[0][d]+V[1][d]+V[2][d]+V[3][d]; }
        for (int r=0;r<6;++r) for (int c=0;c<6;++c) e[oA+r*6+c]=A[r][c];
        for (int i=0;i<36;++i) e[oC+i]=0.0f;
        e[oC+4*6+4]=C2[0][0]; e[oC+4*6+5]=C2[0][1];
        e[oC+5*6+4]=C2[1][0]; e[oC+5*6+5]=C2[1][1];
        for (int r=0;r<6;++r) for (int c=0;c<6;++c) e[oJ+r*6+c]=J[r][c];
    }
}

__global__ void __launch_bounds__(256) scan_level(int d, int srcp) {
    int lane = threadIdx.x & 31;
    int warp = threadIdx.x >> 5;
    if (lane >= 30) return;
    int g = lane/6, r = lane - g*6, base = g*6;
    unsigned mask = 0x3Fu << base;
    int gid = (blockIdx.x*8 + warp)*5 + g;
    if (gid >= TS) return;
    const float* sb = g_buf[srcp];
    float* db = g_buf[srcp^1];
    const float* ej = &sb[gid*ESTR];
    float* dst = &db[gid*ESTR];
    if (gid < d) {
#pragma unroll
        for (int j=0;j<20;++j) dst[r*20+j]=ej[r*20+j];
        return;
    }
    const float* ei = &sb[(gid-d)*ESTR];
    float A1[6],C1[6],J1[6],b1[6],e1[6],A2[6],C2[6],J2[6],b2[6],e2[6];
#pragma unroll
    for (int k=0;k<6;++k){
        A1[k]=ei[oA+r*6+k]; C1[k]=ei[oC+r*6+k]; J1[k]=ei[oJ+r*6+k];
        A2[k]=ej[oA+r*6+k]; C2[k]=ej[oC+r*6+k]; J2[k]=ej[oJ+r*6+k];
        b1[k]=ei[oB+k]; e1[k]=ei[oE+k]; b2[k]=ej[oB+k]; e2[k]=ej[oE+k];
    }
    float Ao[6],Co[6],Jo[6],bo[6],eoo[6];
    compose_rp<float,true>(mask,base,r,A1,C1,J1,b1,e1,A2,C2,J2,b2,e2,Ao,Co,Jo,bo,eoo);
#pragma unroll
    for (int k=0;k<6;++k){ dst[oA+r*6+k]=Ao[k]; dst[oC+r*6+k]=Co[k]; dst[oJ+r*6+k]=Jo[k]; }
    if (r==0){
#pragma unroll
        for (int k=0;k<6;++k){ dst[oB+k]=bo[k]; dst[oE+k]=eoo[k]; }
    }
}

__global__ void ll_terms(const float* __restrict__ track, const float* __restrict__ bs,
                         const float* __restrict__ onp, const float* __restrict__ tnp, int finp) {
    int t = blockIdx.x*blockDim.x + threadIdx.x;
    const double sig2 = (double)onp[0]*(double)onp[0];
    const double q = (double)tnp[0]*(double)tnp[0];
    const double rn = sig2/32.0;
    double llt = 0.0;
    if (t < TS) {
        double m[6], P[6][6];
        if (t == 0) {
            for (int i=0;i<6;++i) m[i]=0.0;
            for (int r=0;r<6;++r) for (int c=0;c<6;++c) P[r][c]=0.0;
            P[0][0]=(double)bs[0]/32.0; P[1][1]=(double)bs[1]/32.0;
            P[2][2]=P[0][0]; P[3][3]=P[1][1]; P[4][4]=1.0; P[5][5]=1.0;
        } else {
            const float* e = &g_buf[finp][(t-1)*ESTR];
            for (int i=0;i<6;++i) m[i]=(double)e[oB+i];
            for (int r=0;r<6;++r) for (int c=0;c<6;++c) P[r][c]=(double)e[oC+r*6+c];
        }
        double mp[6];
        for (int i=0;i<4;++i) mp[i]=m[i];
        mp[4]=m[4]+m[5]; mp[5]=m[5];
        for (int c=0;c<6;++c) P[4][c]+=P[5][c];
        for (int r=0;r<6;++r) P[r][4]+=P[r][5];
        P[4][4]+=q/3.0; P[4][5]+=q*0.5; P[5][4]+=q*0.5; P[5][5]+=q;
        double y0=(double)track[2*t], y1=(double)track[2*t+1];
        double yb[4]={y0,y1,y0,y1};
        double S4[4][4], v[4];
        for (int g=0;g<4;++g){
            int rg=g>>1;
            v[g]=yb[g]-(mp[g]+mp[4+rg]);
            for (int h=0;h<4;++h){
                int rh=h>>1;
                S4[g][h]=P[g][h]+P[g][4+rh]+P[4+rg][h]+P[4+rg][4+rh]+((g==h)?rn:0.0);
            }
        }
        double Si[4][4];
        double det=inv4d(S4,Si);
        double quad=0.0;
        for (int g=0;g<4;++g) for (int h=0;h<4;++h) quad+=v[g]*Si[g][h]*v[h];
        double tf=(double)t;
        double d0=1.0/(1.0/(double)bs[0]+tf/sig2)+sig2;
        double d1=1.0/(1.0/(double)bs[1]+tf/sig2)+sig2;
        double step=128.0*LOG2PI + 62.0*(log(d0)+log(d1))
                  + 4.0*log(32.0) + log(det) + quad;
        llt = -0.5*step;
    }
    __shared__ double sd[128];
    sd[threadIdx.x]=llt; __syncthreads();
    for (int s=64;s>0;s>>=1){ if((int)threadIdx.x<s) sd[threadIdx.x]+=sd[threadIdx.x+s]; __syncthreads(); }
    if (threadIdx.x==0) g_llp[blockIdx.x]=sd[0];
}

// ---- shared-memory cooperative fp64 composition (A,C,J only), no shuffles.
// E layout: [0:36) A, [36:72) C, [72:108) J.
// W layout: [0:72) augmented M, [72:108) T1, [108:144) T2, [144:180) T3,
//           [180] pivot index, [181] pivot reciprocal.
// EVERY thread of the block must call this from the SAME call site.
__device__ __forceinline__ void compose_smem(
    int lt, const double* E1, const double* E2, double* Eo, double* W)
{
    double* M  = W;
    double* T1 = W+72;
    double* T2 = W+108;
    double* T3 = W+144;
    const bool a72 = (lt >= 0 && lt < 72);
    const bool a36 = (lt >= 0 && lt < 36);
    int r12 = a72 ? lt/12 : 0, c12 = a72 ? lt%12 : 0;
    int r6  = a36 ? lt/6  : 0, c6  = a36 ? lt%6  : 0;
    int r6b = (lt>=36 && lt<72) ? (lt-36)/6 : 0, c6b = (lt>=36 && lt<72) ? (lt-36)%6 : 0;

    if (a72) {
        if (c12 < 6) {
            double s = (r12==c12)?1.0:0.0;
#pragma unroll
            for (int k=0;k<6;++k) s += E1[36+r12*6+k]*E2[72+k*6+c12];
            M[r12*12+c12] = s;
        } else {
            M[r12*12+c12] = (r12==(c12-6))?1.0:0.0;
        }
    }
    __syncthreads();
    for (int col=0; col<6; ++col) {
        if (lt == 0) {
            int p=col; double best=fabs(M[col*12+col]);
            for (int x=col+1;x<6;++x){ double v=fabs(M[x*12+col]); if(v>best){best=v;p=x;} }
            W[180] = (double)p;
        }
        __syncthreads();
        int p = (int)W[180];
        if (lt >= 0 && lt < 12 && p != col) {
            double va=M[col*12+lt], vb=M[p*12+lt];
            M[col*12+lt]=vb; M[p*12+lt]=va;
        }
        __syncthreads();
        if (lt == 0) W[181] = 1.0/M[col*12+col];
        if (lt >= 32 && lt < 38) {
            int rr = lt-32;
            T1[rr] = M[rr*12+col];
        }
        __syncthreads();
        if (lt >= 0 && lt < 12) M[col*12+lt] *= W[181];
        __syncthreads();
        if (a72 && r12 != col) M[r12*12+c12] -= T1[r12]*M[col*12+c12];
        __syncthreads();
    }
    if (a36) {
        double s=0;
#pragma unroll
        for (int k=0;k<6;++k) s += M[r6*12+6+k]*E1[k*6+c6];
        T1[r6*6+c6]=s;
    } else if (a72) {
        double s=0;
#pragma unroll
        for (int k=0;k<6;++k) s += E2[72+r6b*6+k]*E1[k*6+c6b];
        T2[r6b*6+c6b]=s;
    }
    __syncthreads();
    if (a36) {
        double s=0;
#pragma unroll
        for (int k=0;k<6;++k) s += E2[r6*6+k]*T1[k*6+c6];
        Eo[r6*6+c6]=s;
    } else if (a72) {
        double s=E1[72+r6b*6+c6b];
#pragma unroll
        for (int k=0;k<6;++k) s += T1[k*6+r6b]*T2[k*6+c6b];
        T3[r6b*6+c6b]=s;
    }
    __syncthreads();
    if (a36) {
        double s=0;
#pragma unroll
        for (int k=0;k<6;++k) s += M[r6*12+6+k]*E1[36+k*6+c6];
        T2[r6*6+c6]=s;
    } else if (a72) {
        Eo[72+r6b*6+c6b] = 0.5*(T3[r6b*6+c6b]+T3[c6b*6+r6b]);
    }
    __syncthreads();
    if (a36) {
        double s=0;
#pragma unroll
        for (int k=0;k<6;++k) s += E2[r6*6+k]*T2[k*6+c6];
        T1[r6*6+c6]=s;
    }
    __syncthreads();
    if (a36) {
        double s=E2[36+r6*6+c6];
#pragma unroll
        for (int k=0;k<6;++k) s += T1[r6*6+k]*E2[c6*6+k];
        T3[r6*6+c6]=s;
    }
    __syncthreads();
    if (a36) Eo[36+r6*6+c6] = 0.5*(T3[r6*6+c6]+T3[c6*6+r6]);
    __syncthreads();
}

// fp64 covariance via binary powering with smem compose; two parallel chains,
// single uniform call site (no divergent barriers).
__global__ void __launch_bounds__(160) cov_power(const float* __restrict__ bs,
                                                 const float* __restrict__ onp,
                                                 const float* __restrict__ tnp) {
    __shared__ double sp[108], sr[108], tp[108], tr[108];
    __shared__ double wP[182], wR[182];
    int tid = threadIdx.x;
    const double sig2 = (double)onp[0]*(double)onp[0];
    const double q = (double)tnp[0]*(double)tnp[0];
    const double rn = sig2/32.0;
    double Qs[2][2]={{q/3.0,q*0.5},{q*0.5,q}};

    if (tid < 6) {
        int r=tid;
        double S4[4][4],Si[4][4];
        for (int gg=0;gg<4;++gg) for (int h=0;h<4;++h)
            S4[gg][h]=Qs[gg>>1][h>>1]+((gg==h)?rn:0.0);
        inv4d(S4,Si);
        double K2[2][4];
        for (int i=0;i<2;++i) for (int gg=0;gg<4;++gg){
            double s=0; for (int h=0;h<4;++h) s+=Qs[i][h>>1]*Si[h][gg]; K2[i][gg]=s; }
        double Ar[6];
#pragma unroll
        for (int c=0;c<6;++c) Ar[c]=(r==c)?1.0:0.0;
        if (r==4) Ar[5]=1.0;
        if (r>=4){
            int i=r-4;
            for (int gg=0; gg<4; ++gg) Ar[gg]-=K2[i][gg];
            double s4=K2[i][0]+K2[i][1], s5=s4+K2[i][2]+K2[i][3];
            Ar[4]-=s4; Ar[5]-=s5;
        }
        double C2m[2][2];
        for (int i=0;i<2;++i) for (int j=0;j<2;++j){
            double s=Qs[i][j];
            for (int gg=0;gg<4;++gg) s-=K2[i][gg]*Qs[gg>>1][j];
            C2m[i][j]=s;
        }
        { double m=0.5*(C2m[0][1]+C2m[1][0]); C2m[0][1]=m; C2m[1][0]=m; }
        double Cr[6]={0,0,0,0,0,0};
        if (r>=4){ Cr[4]=C2m[r-4][0]; Cr[5]=C2m[r-4][1]; }
        double V[4][6];
        for (int gg=0;gg<4;++gg){
            for (int d=0;d<4;++d) V[gg][d]=Si[gg][d];
            V[gg][4]=Si[gg][0]+Si[gg][1];
            V[gg][5]=V[gg][4]+Si[gg][2]+Si[gg][3];
        }
        double Jr[6];
#pragma unroll
        for (int c=0;c<6;++c){
            double s=0;
            for (int gg=0; gg<4; ++gg) if (r==gg) s=V[gg][c];
            if (r==4) s=V[0][c]+V[1][c];
            if (r==5) s=V[0][c]+V[1][c]+V[2][c]+V[3][c];
            Jr[c]=s;
        }
#pragma unroll
        for (int c=0;c<6;++c){
            sp[r*6+c]=Ar[c]; sp[36+r*6+c]=Cr[c]; sp[72+r*6+c]=Jr[c];
            sr[r*6+c]=(r==c)?1.0:0.0; sr[36+r*6+c]=0.0; sr[72+r*6+c]=0.0;
        }
    }
    __syncthreads();
    // partition pointers (uniform call site below)
    const bool isP = (tid < 72);
    int lt = isP ? tid : tid - 72;          // >=72 for tid>=144: inactive
    for (int it=0; it<11; ++it) {
        const double* E1s = isP ? sp : sr;
        double* Eos = isP ? tp : tr;
        double* Ws  = isP ? wP : wR;
        compose_smem(lt, E1s, sp, Eos, Ws);
        __syncthreads();
        if (tid < 108) sp[tid]=tp[tid];
        if (tid >= 36 && tid < 144) sr[tid-36]=tr[tid-36];
        __syncthreads();
    }
    // build e0 into tp (A=0, C=prior-update cov, J=0)
    if (tid < 6) {
        int r=tid;
        double P[36];
#pragma unroll
        for (int i=0;i<36;++i) P[i]=0.0;
        P[0]=(double)bs[0]/32.0; P[7]=(double)bs[1]/32.0;
        P[14]=P[0]; P[21]=P[7];
        P[4*6+4]=2.0+Qs[0][0]; P[4*6+5]=1.0+Qs[0][1];
        P[5*6+4]=1.0+Qs[0][1]; P[5*6+5]=1.0+Qs[1][1];
        double PH[24];
        for (int x=0;x<6;++x) for (int gg=0;gg<4;++gg) PH[x*4+gg]=P[x*6+gg]+P[x*6+4+(gg>>1)];
        double S4f[4][4], Sif[4][4];
        for (int gg=0;gg<4;++gg) for (int h=0;h<4;++h)
            S4f[gg][h]=PH[gg*4+h]+PH[(4+(gg>>1))*4+h]+((gg==h)?rn:0.0);
        inv4d(S4f,Sif);
        double Kr[4];
        for (int gg=0;gg<4;++gg){ double s=0;
            for (int h=0;h<4;++h) s+=PH[r*4+h]*Sif[h][gg]; Kr[gg]=s; }
#pragma unroll
        for (int c=0;c<6;++c){
            double s=P[r*6+c];
            for (int gg=0;gg<4;++gg) s-=Kr[gg]*PH[c*4+gg];
            tp[r*6+c]=0.0; tp[36+r*6+c]=s; tp[72+r*6+c]=0.0;
        }
    }
    __syncthreads();
    compose_smem((tid<72)?tid:-1, tp, sr, tr, wP);
    __syncthreads();
    if (tid < 36) g_P6[tid] = tr[36+tid];
}

__global__ void __launch_bounds__(256)
finalize(const float* __restrict__ bs, const float* __restrict__ onp,
         const float* __restrict__ tnp,
         float* __restrict__ out, int out_size) {
    __shared__ double sLam4[4], sPhi[4][4], sE[4][2], sSsInv[2][2], sPu[3];
    __shared__ double sll;
    if (threadIdx.x == 0) {
        const double sig2 = (double)onp[0]*(double)onp[0];
        const double q = (double)tnp[0]*(double)tnp[0];
        double ll=0.0;
        for (int i=0;i<16;++i) ll+=g_llp[i];
        sll=ll;
        double P6[6][6];
        for (int r=0;r<6;++r) for (int c=0;c<6;++c) P6[r][c]=g_P6[r*6+c];
        double aT0=1.0/(1.0/(double)bs[0]+2048.0/sig2);
        double aT1=1.0/(1.0/(double)bs[1]+2048.0/sig2);
        double a[4]={aT0,aT1,aT0,aT1};
        double B[4][4], C[4][2];
        for (int g=0;g<4;++g){
            for (int h=0;h<4;++h) B[g][h]=P6[g][h]-((g==h)?a[g]/32.0:0.0);
            C[g][0]=P6[g][4]; C[g][1]=P6[g][5];
        }
        double p00=P6[4][4], p02=P6[4][5], p22=P6[5][5];
        double La[4]={1.0/a[0],1.0/a[1],1.0/a[2],1.0/a[3]};
        double Xb[4][4];
        for (int g=0;g<4;++g) for (int h=0;h<4;++h)
            Xb[g][h]=((g==h)?1.0:0.0)+32.0*La[g]*B[g][h];
        double Yb[4][4]; inv4d(Xb,Yb);
        double G[4][4];
        for (int g=0;g<4;++g) for (int h=0;h<4;++h){
            double s=0; for (int k=0;k<4;++k) s+=B[g][k]*Yb[k][h];
            G[g][h]=La[g]*s*La[h];
        }
        double M4[4][4];
        for (int g=0;g<4;++g) for (int h=0;h<4;++h)
            M4[g][h]=((g==h)?La[g]:0.0)-32.0*G[g][h];
        double MC[4][2];
        for (int g=0;g<4;++g){
            double t0=0,t1=0;
            for (int k=0;k<4;++k){ t0+=M4[g][k]*C[k][0]; t1+=M4[g][k]*C[k][1]; }
            MC[g][0]=t0; MC[g][1]=t1;
        }
        double ss00=p00, ss01=p02, ss11=p22;
        for (int g=0;g<4;++g){
            ss00-=32.0*C[g][0]*MC[g][0];
            ss01-=32.0*C[g][0]*MC[g][1];
            ss11-=32.0*C[g][1]*MC[g][1];
        }
        {
            double det=ss00*ss11-ss01*ss01;
            double id=1.0/det;
            sSsInv[0][0]=ss11*id; sSsInv[0][1]=-ss01*id;
            sSsInv[1][0]=-ss01*id; sSsInv[1][1]=ss00*id;
        }
        for (int g=0;g<4;++g){
            sE[g][0]=-(MC[g][0]*sSsInv[0][0]+MC[g][1]*sSsInv[1][0]);
            sE[g][1]=-(MC[g][0]*sSsInv[0][1]+MC[g][1]*sSsInv[1][1]);
        }
        for (int g=0;g<4;++g) for (int h=0;h<4;++h)
            sPhi[g][h]=-G[g][h]-(sE[g][0]*MC[h][0]+sE[g][1]*MC[h][1]);
        for (int g=0;g<4;++g) sLam4[g]=La[g];
        {
            const double td=2048.0;
            double sum00=td/3.0+td*(td-1.0)/2.0+(td-1.0)*td*(2.0*td-1.0)/6.0;
            double sum01=td/2.0+td*(td-1.0)/2.0;
            double pu00=1.0+td*td+q*sum00;
            double pu01=td+q*sum01;
            double pu11=1.0+q*td;
            double det=pu00*pu11-pu01*pu01, idd=1.0/det;
            sPu[0]=pu11*idd; sPu[1]=-pu01*idd; sPu[2]=pu00*idd;
        }
    }
    __syncthreads();
    const int off = (out_size >= 17425) ? 1 : 0;
    if (threadIdx.x == 0 && off) out[0] = (float)sll;
    for (int ecnt = threadIdx.x; ecnt < 17424; ecnt += blockDim.x) {
        int r = ecnt / 132, c = ecnt % 132;
        double val = 0.0;
        if (r < 128 && c < 128) {
            int g=(r&1)+((r>=64)?2:0), h=(c&1)+((c>=64)?2:0);
            val=sPhi[g][h];
            if (r==c) val+=sLam4[g];
        } else if (r < 128) {
            int g=(r&1)+((r>=64)?2:0), j=c-128;
            if (j==0) val=sE[g][0]; else if (j==2) val=sE[g][1];
        } else if (c < 128) {
            int h=(c&1)+((c>=64)?2:0), i=r-128;
            if (i==0) val=sE[h][0]; else if (i==2) val=sE[h][1];
        } else {
            int i=r-128, j=c-128;
            if ((i==0||i==2)&&(j==0||j==2)) val=sSsInv[i>>1][j>>1];
            else if (i==1&&j==1) val=sPu[0];
            else if ((i==1&&j==3)||(i==3&&j==1)) val=sPu[1];
            else if (i==3&&j==3) val=sPu[2];
        }
        out[off+ecnt]=(float)val;
    }
}

extern "C" void kernel_launch(void* const* d_in, const int* in_sizes, int n_in,
                              void* d_out, int out_size) {
    const float* track       = (const float*)d_in[0];
    const float* bias_scales = (const float*)d_in[1];
    const float* obs_noise   = (const float*)d_in[2];
    const float* trans_noise = (const float*)d_in[3];
    float* out = (float*)d_out;
    init_elems<<<16,128>>>(track, bias_scales, obs_noise, trans_noise);
    int p = 0;
    for (int d=1; d<TS; d<<=1) { scan_level<<<52,256>>>(d, p); p^=1; }
    ll_terms<<<16,128>>>(track, bias_scales, obs_noise, trans_noise, p);
    cov_power<<<1,160>>>(bias_scales, obs_noise, trans_noise);
    finalize<<<1,256>>>(bias_scales, obs_noise, trans_noise, out, out_size);
}

// round 16
// speedup vs baseline: 3.0313x; 1.0467x over previous
#include <cuda_runtime.h>
#include <math.h>

#define TS 2048
#define ESTR 128
#define oA 0
#define oB 36
#define oC 42
#define oE 78
#define oJ 84
#define LOG2PI 1.8378770664093454836

__device__ float g_buf[2][TS*ESTR];
__device__ double g_llp[16];

template<typename T> __device__ __forceinline__ T tabs(T x){ return x < T(0) ? -x : x; }

__device__ __forceinline__ float inv4f(const float A[4][4], float R[4][4]) {
    float a00=A[0][0],a01=A[0][1],a02=A[0][2],a03=A[0][3];
    float a10=A[1][0],a11=A[1][1],a12=A[1][2],a13=A[1][3];
    float a20=A[2][0],a21=A[2][1],a22=A[2][2],a23=A[2][3];
    float a30=A[3][0],a31=A[3][1],a32=A[3][2],a33=A[3][3];
    float s0=a00*a11-a10*a01,s1=a00*a12-a10*a02,s2=a00*a13-a10*a03;
    float s3=a01*a12-a11*a02,s4=a01*a13-a11*a03,s5=a02*a13-a12*a03;
    float c5=a22*a33-a32*a23,c4=a21*a33-a31*a23,c3=a21*a32-a31*a22;
    float c2=a20*a33-a30*a23,c1=a20*a32-a30*a22,c0=a20*a31-a30*a21;
    float det=s0*c5-s1*c4+s2*c3+s3*c2-s4*c1+s5*c0;
    float id=__fdividef(1.0f,det);
    R[0][0]=( a11*c5-a12*c4+a13*c3)*id; R[0][1]=(-a01*c5+a02*c4-a03*c3)*id;
    R[0][2]=( a31*s5-a32*s4+a33*s3)*id; R[0][3]=(-a21*s5+a22*s4-a23*s3)*id;
    R[1][0]=(-a10*c5+a12*c2-a13*c1)*id; R[1][1]=( a00*c5-a02*c2+a03*c1)*id;
    R[1][2]=(-a30*s5+a32*s2-a33*s1)*id; R[1][3]=( a20*s5-a22*s2+a23*s1)*id;
    R[2][0]=( a10*c4-a11*c2+a13*c0)*id; R[2][1]=(-a00*c4+a01*c2-a03*c0)*id;
    R[2][2]=( a30*s4-a31*s2+a33*s0)*id; R[2][3]=(-a20*s4+a21*s2-a23*s0)*id;
    R[3][0]=(-a10*c3+a11*c1-a12*c0)*id; R[3][1]=( a00*c3-a01*c1+a02*c0)*id;
    R[3][2]=(-a30*s3+a31*s1-a32*s0)*id; R[3][3]=( a20*s3-a21*s1+a22*s0)*id;
    return det;
}

__device__ __forceinline__ double inv4d(const double A[4][4], double R[4][4]) {
    double a00=A[0][0],a01=A[0][1],a02=A[0][2],a03=A[0][3];
    double a10=A[1][0],a11=A[1][1],a12=A[1][2],a13=A[1][3];
    double a20=A[2][0],a21=A[2][1],a22=A[2][2],a23=A[2][3];
    double a30=A[3][0],a31=A[3][1],a32=A[3][2],a33=A[3][3];
    double s0=a00*a11-a10*a01,s1=a00*a12-a10*a02,s2=a00*a13-a10*a03;
    double s3=a01*a12-a11*a02,s4=a01*a13-a11*a03,s5=a02*a13-a12*a03;
    double c5=a22*a33-a32*a23,c4=a21*a33-a31*a23,c3=a21*a32-a31*a22;
    double c2=a20*a33-a30*a23,c1=a20*a32-a30*a22,c0=a20*a31-a30*a21;
    double det=s0*c5-s1*c4+s2*c3+s3*c2-s4*c1+s5*c0;
    double id=1.0/det;
    R[0][0]=( a11*c5-a12*c4+a13*c3)*id; R[0][1]=(-a01*c5+a02*c4-a03*c3)*id;
    R[0][2]=( a31*s5-a32*s4+a33*s3)*id; R[0][3]=(-a21*s5+a22*s4-a23*s3)*id;
    R[1][0]=(-a10*c5+a12*c2-a13*c1)*id; R[1][1]=( a00*c5-a02*c2+a03*c1)*id;
    R[1][2]=(-a30*s5+a32*s2-a33*s1)*id; R[1][3]=( a20*s5-a22*s2+a23*s1)*id;
    R[2][0]=( a10*c4-a11*c2+a13*c0)*id; R[2][1]=(-a00*c4+a01*c2-a03*c0)*id;
    R[2][2]=( a30*s4-a31*s2+a33*s0)*id; R[2][3]=(-a20*s4+a21*s2-a23*s0)*id;
    R[3][0]=(-a10*c3+a11*c1-a12*c0)*id; R[3][1]=( a00*c3-a01*c1+a02*c0)*id;
    R[3][2]=(-a30*s3+a31*s1-a32*s0)*id; R[3][3]=( a20*s3-a21*s1+a22*s0)*id;
    return det;
}

// Row-parallel Sarkka composition. UNPIVOTED GJ: M = I + C1*J2 is similar to
// an SPD matrix with eigenvalues >= 1, so elimination without pivoting is
// stable; removes ~120 serial-chain shuffles per compose.
template<typename T, bool VEC>
__device__ __forceinline__ void compose_rp(
    unsigned mask, int base, int r,
    const T* A1, const T* C1, const T* J1, const T* b1, const T* e1,
    const T* A2, const T* C2, const T* J2, const T* b2, const T* e2,
    T* Ao, T* Co, T* Jo, T* bo, T* eo)
{
    T M[12];
#pragma unroll
    for (int c=0;c<6;++c){
        T s=(r==c)?T(1):T(0);
#pragma unroll
        for (int k=0;k<6;++k) s += C1[k]*__shfl_sync(mask, J2[c], base+k);
        M[c]=s; M[6+c]=(r==c)?T(1):T(0);
    }
#pragma unroll
    for (int col=0;col<6;++col){
        T piv=__shfl_sync(mask, M[col], base+col);
        T ip=T(1)/piv;
        if (r==col){
#pragma unroll
            for (int j=0;j<12;++j) M[j]*=ip;
        }
        T f=M[col];
        T pr[12];
#pragma unroll
        for (int j=0;j<12;++j) pr[j]=__shfl_sync(mask, M[j], base+col);
        if (r!=col){
#pragma unroll
            for (int j=0;j<12;++j) M[j]-=f*pr[j];
        }
    }
    T D[6];
#pragma unroll
    for (int c=0;c<6;++c) D[c]=M[6+c];
    T T1[6];
#pragma unroll
    for (int c=0;c<6;++c){ T s=T(0);
#pragma unroll
        for (int k=0;k<6;++k) s+=D[k]*__shfl_sync(mask, A1[c], base+k);
        T1[c]=s; }
#pragma unroll
    for (int c=0;c<6;++c){ T s=T(0);
#pragma unroll
        for (int k=0;k<6;++k) s+=A2[k]*__shfl_sync(mask, T1[c], base+k);
        Ao[c]=s; }
    if (VEC) {
        T u[6], wv[6];
#pragma unroll
        for (int i=0;i<6;++i){ T s=b1[i];
#pragma unroll
            for (int k=0;k<6;++k) s+=__shfl_sync(mask, C1[k], base+i)*e2[k];
            u[i]=s; }
#pragma unroll
        for (int i=0;i<6;++i){ T s=T(0);
#pragma unroll
            for (int k=0;k<6;++k) s+=__shfl_sync(mask, D[k], base+i)*u[k];
            wv[i]=s; }
#pragma unroll
        for (int i=0;i<6;++i){ T s=b2[i];
#pragma unroll
            for (int k=0;k<6;++k) s+=__shfl_sync(mask, A2[k], base+i)*wv[k];
            bo[i]=s; }
        T rv[6];
#pragma unroll
        for (int k=0;k<6;++k){ T s=e2[k];
#pragma unroll
            for (int m=0;m<6;++m) s-=__shfl_sync(mask, J2[m], base+k)*b1[m];
            rv[k]=s; }
#pragma unroll
        for (int c=0;c<6;++c){ T s=e1[c];
#pragma unroll
            for (int k=0;k<6;++k) s+=__shfl_sync(mask, T1[c], base+k)*rv[k];
            eo[c]=s; }
    }
    T S[6], Tt[6];
#pragma unroll
    for (int c=0;c<6;++c){ T s=T(0);
#pragma unroll
        for (int k=0;k<6;++k) s+=D[k]*__shfl_sync(mask, C1[c], base+k);
        S[c]=s; }
#pragma unroll
    for (int c=0;c<6;++c){ T s=T(0);
#pragma unroll
        for (int k=0;k<6;++k) s+=A2[k]*__shfl_sync(mask, S[c], base+k);
        Tt[c]=s; }
#pragma unroll
    for (int c=0;c<6;++c){ T s=C2[c];
#pragma unroll
        for (int k=0;k<6;++k) s+=Tt[k]*__shfl_sync(mask, A2[k], base+c);
        Co[c]=s; }
    T T5[6];
#pragma unroll
    for (int c=0;c<6;++c){ T s=T(0);
#pragma unroll
        for (int k=0;k<6;++k) s+=J2[k]*__shfl_sync(mask, A1[c], base+k);
        T5[c]=s; }
    T T1t[6];
#pragma unroll
    for (int j=0;j<6;++j){
#pragma unroll
        for (int k=0;k<6;++k){
            T w2=__shfl_sync(mask, T1[j], base+k);
            if (r==j) T1t[k]=w2;
        }
    }
#pragma unroll
    for (int c=0;c<6;++c){ T s=J1[c];
#pragma unroll
        for (int k=0;k<6;++k) s+=T1t[k]*__shfl_sync(mask, T5[c], base+k);
        Jo[c]=s; }
}

__global__ void init_elems(const float* __restrict__ track, const float* __restrict__ bs,
                           const float* __restrict__ onp, const float* __restrict__ tnp) {
    int t = blockIdx.x*blockDim.x + threadIdx.x;
    if (t >= TS) return;
    float* e = &g_buf[0][t*ESTR];
    const float sig2 = onp[0]*onp[0];
    const float q = tnp[0]*tnp[0];
    const float rn = sig2/32.0f;
    float Qs[2][2] = {{q/3.0f, q*0.5f},{q*0.5f, q}};
    float y0 = track[2*t], y1 = track[2*t+1];
    float yb[4] = {y0,y1,y0,y1};
    if (t == 0) {
        float P[6][6];
        for (int r=0;r<6;++r) for (int c=0;c<6;++c) P[r][c]=0.0f;
        P[0][0]=bs[0]/32.0f; P[1][1]=bs[1]/32.0f;
        P[2][2]=P[0][0]; P[3][3]=P[1][1];
        P[4][4]=2.0f+Qs[0][0]; P[4][5]=1.0f+Qs[0][1];
        P[5][4]=1.0f+Qs[1][0]; P[5][5]=1.0f+Qs[1][1];
        float PH[6][4];
        for (int r=0;r<6;++r) for (int g=0;g<4;++g) PH[r][g]=P[r][g]+P[r][4+(g>>1)];
        float S4[4][4];
        for (int g=0;g<4;++g) for (int h=0;h<4;++h)
            S4[g][h]=PH[g][h]+PH[4+(g>>1)][h]+((g==h)?rn:0.0f);
        float Si[4][4]; inv4f(S4,Si);
        float K[6][4];
        for (int r=0;r<6;++r) for (int g=0;g<4;++g){
            float s=0; for (int h=0;h<4;++h) s+=PH[r][h]*Si[h][g]; K[r][g]=s; }
        for (int i=0;i<36;++i) e[oA+i]=0.0f;
        for (int r=0;r<6;++r){ float s=0; for (int g=0;g<4;++g) s+=K[r][g]*yb[g]; e[oB+r]=s; }
        for (int r=0;r<6;++r) for (int c=0;c<6;++c){
            float s=P[r][c]; for (int g=0;g<4;++g) s-=K[r][g]*PH[c][g];
            e[oC+r*6+c]=s;
        }
        for (int r=0;r<6;++r) for (int c=r+1;c<6;++c){
            float m=0.5f*(e[oC+r*6+c]+e[oC+c*6+r]); e[oC+r*6+c]=m; e[oC+c*6+r]=m; }
        for (int i=0;i<6;++i) e[oE+i]=0.0f;
        for (int i=0;i<36;++i) e[oJ+i]=0.0f;
    } else {
        float S4[4][4];
        for (int g=0;g<4;++g) for (int h=0;h<4;++h)
            S4[g][h]=Qs[g>>1][h>>1]+((g==h)?rn:0.0f);
        float Si[4][4]; inv4f(S4,Si);
        float K2[2][4];
        for (int i=0;i<2;++i) for (int g=0;g<4;++g){
            float s=0; for (int h=0;h<4;++h) s+=Qs[i][h>>1]*Si[h][g]; K2[i][g]=s; }
        float A[6][6];
        for (int r=0;r<6;++r) for (int c=0;c<6;++c) A[r][c]=(r==c)?1.0f:0.0f;
        A[4][5]=1.0f;
        for (int i=0;i<2;++i){
            for (int g=0;g<4;++g) A[4+i][g]-=K2[i][g];
            float s4=K2[i][0]+K2[i][1];
            float s5=s4+K2[i][2]+K2[i][3];
            A[4+i][4]-=s4; A[4+i][5]-=s5;
        }
        float C2[2][2];
        for (int i=0;i<2;++i) for (int j=0;j<2;++j){
            float s=Qs[i][j];
            for (int g=0;g<4;++g) s-=K2[i][g]*Qs[g>>1][j];
            C2[i][j]=s;
        }
        { float m=0.5f*(C2[0][1]+C2[1][0]); C2[0][1]=m; C2[1][0]=m; }
        for (int r=0;r<6;++r) e[oB+r]=0.0f;
        for (int i=0;i<2;++i){ float s=0; for (int g=0;g<4;++g) s+=K2[i][g]*yb[g]; e[oB+4+i]=s; }
        float u[4];
        for (int g=0;g<4;++g){ float s=0; for (int h=0;h<4;++h) s+=Si[g][h]*yb[h]; u[g]=s; }
        for (int c=0;c<4;++c) e[oE+c]=u[c];
        e[oE+4]=u[0]+u[1]; e[oE+5]=u[0]+u[1]+u[2]+u[3];
        float V[4][6];
        for (int g=0;g<4;++g){
            for (int d=0;d<4;++d) V[g][d]=Si[g][d];
            V[g][4]=Si[g][0]+Si[g][1];
            V[g][5]=Si[g][0]+Si[g][1]+Si[g][2]+Si[g][3];
        }
        float J[6][6];
        for (int c=0;c<4;++c) for (int d=0;d<6;++d) J[c][d]=V[c][d];
        for (int d=0;d<6;++d){ J[4][d]=V[0][d]+V[1][d]; J[5][d]=V[0][d]+V[1][d]+V[2][d]+V[3][d]; }
        for (int r=0;r<6;++r) for (int c=0;c<6;++c) e[oA+r*6+c]=A[r][c];
        for (int i=0;i<36;++i) e[oC+i]=0.0f;
        e[oC+4*6+4]=C2[0][0]; e[oC+4*6+5]=C2[0][1];
        e[oC+5*6+4]=C2[1][0]; e[oC+5*6+5]=C2[1][1];
        for (int r=0;r<6;++r) for (int c=0;c<6;++c) e[oJ+r*6+c]=J[r][c];
    }
}

__global__ void __launch_bounds__(256) scan_level(int d, int srcp) {
    int lane = threadIdx.x & 31;
    int warp = threadIdx.x >> 5;
    if (lane >= 30) return;
    int g = lane/6, r = lane - g*6, base = g*6;
    unsigned mask = 0x3Fu << base;
    int gid = (blockIdx.x*8 + warp)*5 + g;
    if (gid >= TS) return;
    const float* sb = g_buf[srcp];
    float* db = g_buf[srcp^1];
    const float* ej = &sb[gid*ESTR];
    float* dst = &db[gid*ESTR];
    if (gid < d) {
#pragma unroll
        for (int j=0;j<20;++j) dst[r*20+j]=ej[r*20+j];
        return;
    }
    const float* ei = &sb[(gid-d)*ESTR];
    float A1[6],C1[6],J1[6],b1[6],e1[6],A2[6],C2[6],J2[6],b2[6],e2[6];
#pragma unroll
    for (int k=0;k<6;++k){
        A1[k]=ei[oA+r*6+k]; C1[k]=ei[oC+r*6+k]; J1[k]=ei[oJ+r*6+k];
        A2[k]=ej[oA+r*6+k]; C2[k]=ej[oC+r*6+k]; J2[k]=ej[oJ+r*6+k];
        b1[k]=ei[oB+k]; e1[k]=ei[oE+k]; b2[k]=ej[oB+k]; e2[k]=ej[oE+k];
    }
    float Ao[6],Co[6],Jo[6],bo[6],eoo[6];
    compose_rp<float,true>(mask,base,r,A1,C1,J1,b1,e1,A2,C2,J2,b2,e2,Ao,Co,Jo,bo,eoo);
#pragma unroll
    for (int k=0;k<6;++k){ dst[oA+r*6+k]=Ao[k]; dst[oC+r*6+k]=Co[k]; dst[oJ+r*6+k]=Jo[k]; }
    if (r==0){
#pragma unroll
        for (int k=0;k<6;++k){ dst[oB+k]=bo[k]; dst[oE+k]=eoo[k]; }
    }
}

__global__ void ll_terms(const float* __restrict__ track, const float* __restrict__ bs,
                         const float* __restrict__ onp, const float* __restrict__ tnp, int finp) {
    int t = blockIdx.x*blockDim.x + threadIdx.x;
    const double sig2 = (double)onp[0]*(double)onp[0];
    const double q = (double)tnp[0]*(double)tnp[0];
    const double rn = sig2/32.0;
    double llt = 0.0;
    if (t < TS) {
        double m[6], P[6][6];
        if (t == 0) {
            for (int i=0;i<6;++i) m[i]=0.0;
            for (int r=0;r<6;++r) for (int c=0;c<6;++c) P[r][c]=0.0;
            P[0][0]=(double)bs[0]/32.0; P[1][1]=(double)bs[1]/32.0;
            P[2][2]=P[0][0]; P[3][3]=P[1][1]; P[4][4]=1.0; P[5][5]=1.0;
        } else {
            const float* e = &g_buf[finp][(t-1)*ESTR];
            for (int i=0;i<6;++i) m[i]=(double)e[oB+i];
            for (int r=0;r<6;++r) for (int c=0;c<6;++c) P[r][c]=(double)e[oC+r*6+c];
        }
        double mp[6];
        for (int i=0;i<4;++i) mp[i]=m[i];
        mp[4]=m[4]+m[5]; mp[5]=m[5];
        for (int c=0;c<6;++c) P[4][c]+=P[5][c];
        for (int r=0;r<6;++r) P[r][4]+=P[r][5];
        P[4][4]+=q/3.0; P[4][5]+=q*0.5; P[5][4]+=q*0.5; P[5][5]+=q;
        double y0=(double)track[2*t], y1=(double)track[2*t+1];
        double yb[4]={y0,y1,y0,y1};
        double S4[4][4], v[4];
        for (int g=0;g<4;++g){
            int rg=g>>1;
            v[g]=yb[g]-(mp[g]+mp[4+rg]);
            for (int h=0;h<4;++h){
                int rh=h>>1;
                S4[g][h]=P[g][h]+P[g][4+rh]+P[4+rg][h]+P[4+rg][4+rh]+((g==h)?rn:0.0);
            }
        }
        double Si[4][4];
        double det=inv4d(S4,Si);
        double quad=0.0;
        for (int g=0;g<4;++g) for (int h=0;h<4;++h) quad+=v[g]*Si[g][h]*v[h];
        double tf=(double)t;
        double d0=1.0/(1.0/(double)bs[0]+tf/sig2)+sig2;
        double d1=1.0/(1.0/(double)bs[1]+tf/sig2)+sig2;
        double step=128.0*LOG2PI + 62.0*(log(d0)+log(d1))
                  + 4.0*log(32.0) + log(det) + quad;
        llt = -0.5*step;
    }
    __shared__ double sd[128];
    sd[threadIdx.x]=llt; __syncthreads();
    for (int s=64;s>0;s>>=1){ if((int)threadIdx.x<s) sd[threadIdx.x]+=sd[threadIdx.x+s]; __syncthreads(); }
    if (threadIdx.x==0) g_llp[blockIdx.x]=sd[0];
}

// ---- shared-memory cooperative fp64 composition (A,C,J only), no shuffles.
// EVERY thread of the block must reach this from the SAME call site.
__device__ __forceinline__ void compose_smem(
    int lt, const double* E1, const double* E2, double* Eo, double* W)
{
    double* M  = W;
    double* T1 = W+72;
    double* T2 = W+108;
    double* T3 = W+144;
    const bool a72 = (lt >= 0 && lt < 72);
    const bool a36 = (lt >= 0 && lt < 36);
    int r12 = a72 ? lt/12 : 0, c12 = a72 ? lt%12 : 0;
    int r6  = a36 ? lt/6  : 0, c6  = a36 ? lt%6  : 0;
    int r6b = (lt>=36 && lt<72) ? (lt-36)/6 : 0, c6b = (lt>=36 && lt<72) ? (lt-36)%6 : 0;

    if (a72) {
        if (c12 < 6) {
            double s = (r12==c12)?1.0:0.0;
#pragma unroll
            for (int k=0;k<6;++k) s += E1[36+r12*6+k]*E2[72+k*6+c12];
            M[r12*12+c12] = s;
        } else {
            M[r12*12+c12] = (r12==(c12-6))?1.0:0.0;
        }
    }
    __syncthreads();
    for (int col=0; col<6; ++col) {
        if (lt == 0) {
            int p=col; double best=fabs(M[col*12+col]);
            for (int x=col+1;x<6;++x){ double v=fabs(M[x*12+col]); if(v>best){best=v;p=x;} }
            W[180] = (double)p;
        }
        __syncthreads();
        int p = (int)W[180];
        if (lt >= 0 && lt < 12 && p != col) {
            double va=M[col*12+lt], vb=M[p*12+lt];
            M[col*12+lt]=vb; M[p*12+lt]=va;
        }
        __syncthreads();
        if (lt == 0) W[181] = 1.0/M[col*12+col];
        if (lt >= 32 && lt < 38) {
            int rr = lt-32;
            T1[rr] = M[rr*12+col];
        }
        __syncthreads();
        if (lt >= 0 && lt < 12) M[col*12+lt] *= W[181];
        __syncthreads();
        if (a72 && r12 != col) M[r12*12+c12] -= T1[r12]*M[col*12+c12];
        __syncthreads();
    }
    if (a36) {
        double s=0;
#pragma unroll
        for (int k=0;k<6;++k) s += M[r6*12+6+k]*E1[k*6+c6];
        T1[r6*6+c6]=s;
    } else if (a72) {
        double s=0;
#pragma unroll
        for (int k=0;k<6;++k) s += E2[72+r6b*6+k]*E1[k*6+c6b];
        T2[r6b*6+c6b]=s;
    }
    __syncthreads();
    if (a36) {
        double s=0;
#pragma unroll
        for (int k=0;k<6;++k) s += E2[r6*6+k]*T1[k*6+c6];
        Eo[r6*6+c6]=s;
    } else if (a72) {
        double s=E1[72+r6b*6+c6b];
#pragma unroll
        for (int k=0;k<6;++k) s += T1[k*6+r6b]*T2[k*6+c6b];
        T3[r6b*6+c6b]=s;
    }
    __syncthreads();
    if (a36) {
        double s=0;
#pragma unroll
        for (int k=0;k<6;++k) s += M[r6*12+6+k]*E1[36+k*6+c6];
        T2[r6*6+c6]=s;
    } else if (a72) {
        Eo[72+r6b*6+c6b] = 0.5*(T3[r6b*6+c6b]+T3[c6b*6+r6b]);
    }
    __syncthreads();
    if (a36) {
        double s=0;
#pragma unroll
        for (int k=0;k<6;++k) s += E2[r6*6+k]*T2[k*6+c6];
        T1[r6*6+c6]=s;
    }
    __syncthreads();
    if (a36) {
        double s=E2[36+r6*6+c6];
#pragma unroll
        for (int k=0;k<6;++k) s += T1[r6*6+k]*E2[c6*6+k];
        T3[r6*6+c6]=s;
    }
    __syncthreads();
    if (a36) Eo[36+r6*6+c6] = 0.5*(T3[r6*6+c6]+T3[c6*6+r6]);
    __syncthreads();
}

// merged: fp64 binary powering (smem compose, uniform barriers) + assembly + output
__global__ void __launch_bounds__(256)
cov_finalize(const float* __restrict__ bs, const float* __restrict__ onp,
             const float* __restrict__ tnp,
             float* __restrict__ out, int out_size) {
    __shared__ double sp[108], sr[108], tp[108], tr[108];
    __shared__ double wP[182], wR[182];
    __shared__ double sLam4[4], sPhi[4][4], sE[4][2], sSsInv[2][2], sPu[3];
    __shared__ double sll;
    int tid = threadIdx.x;
    const double sig2 = (double)onp[0]*(double)onp[0];
    const double q = (double)tnp[0]*(double)tnp[0];
    const double rn = sig2/32.0;
    double Qs[2][2]={{q/3.0,q*0.5},{q*0.5,q}};

    if (tid < 6) {
        int r=tid;
        double S4[4][4],Si[4][4];
        for (int gg=0;gg<4;++gg) for (int h=0;h<4;++h)
            S4[gg][h]=Qs[gg>>1][h>>1]+((gg==h)?rn:0.0);
        inv4d(S4,Si);
        double K2[2][4];
        for (int i=0;i<2;++i) for (int gg=0;gg<4;++gg){
            double s=0; for (int h=0;h<4;++h) s+=Qs[i][h>>1]*Si[h][gg]; K2[i][gg]=s; }
        double Ar[6];
#pragma unroll
        for (int c=0;c<6;++c) Ar[c]=(r==c)?1.0:0.0;
        if (r==4) Ar[5]=1.0;
        if (r>=4){
            int i=r-4;
            for (int gg=0; gg<4; ++gg) Ar[gg]-=K2[i][gg];
            double s4=K2[i][0]+K2[i][1], s5=s4+K2[i][2]+K2[i][3];
            Ar[4]-=s4; Ar[5]-=s5;
        }
        double C2m[2][2];
        for (int i=0;i<2;++i) for (int j=0;j<2;++j){
            double s=Qs[i][j];
            for (int gg=0;gg<4;++gg) s-=K2[i][gg]*Qs[gg>>1][j];
            C2m[i][j]=s;
        }
        { double m=0.5*(C2m[0][1]+C2m[1][0]); C2m[0][1]=m; C2m[1][0]=m; }
        double Cr[6]={0,0,0,0,0,0};
        if (r>=4){ Cr[4]=C2m[r-4][0]; Cr[5]=C2m[r-4][1]; }
        double V[4][6];
        for (int gg=0;gg<4;++gg){
            for (int d=0;d<4;++d) V[gg][d]=Si[gg][d];
            V[gg][4]=Si[gg][0]+Si[gg][1];
            V[gg][5]=V[gg][4]+Si[gg][2]+Si[gg][3];
        }
        double Jr[6];
#pragma unroll
        for (int c=0;c<6;++c){
            double s=0;
            for (int gg=0; gg<4; ++gg) if (r==gg) s=V[gg][c];
            if (r==4) s=V[0][c]+V[1][c];
            if (r==5) s=V[0][c]+V[1][c]+V[2][c]+V[3][c];
            Jr[c]=s;
        }
#pragma unroll
        for (int c=0;c<6;++c){
            sp[r*6+c]=Ar[c]; sp[36+r*6+c]=Cr[c]; sp[72+r*6+c]=Jr[c];
            sr[r*6+c]=(r==c)?1.0:0.0; sr[36+r*6+c]=0.0; sr[72+r*6+c]=0.0;
        }
    }
    __syncthreads();
    const bool isP = (tid < 72);
    int lt = isP ? tid : tid - 72;     // tid>=144 -> lt>=72 inactive
    for (int it=0; it<11; ++it) {
        const double* E1s = isP ? sp : sr;
        double* Eos = isP ? tp : tr;
        double* Ws  = isP ? wP : wR;
        compose_smem(lt, E1s, sp, Eos, Ws);
        __syncthreads();
        if (tid < 108) sp[tid]=tp[tid];
        if (tid >= 36 && tid < 144) sr[tid-36]=tr[tid-36];
        __syncthreads();
    }
    if (tid < 6) {
        int r=tid;
        double P[36];
#pragma unroll
        for (int i=0;i<36;++i) P[i]=0.0;
        P[0]=(double)bs[0]/32.0; P[7]=(double)bs[1]/32.0;
        P[14]=P[0]; P[21]=P[7];
        P[4*6+4]=2.0+Qs[0][0]; P[4*6+5]=1.0+Qs[0][1];
        P[5*6+4]=1.0+Qs[0][1]; P[5*6+5]=1.0+Qs[1][1];
        double PH[24];
        for (int x=0;x<6;++x) for (int gg=0;gg<4;++gg) PH[x*4+gg]=P[x*6+gg]+P[x*6+4+(gg>>1)];
        double S4f[4][4], Sif[4][4];
        for (int gg=0;gg<4;++gg) for (int h=0;h<4;++h)
            S4f[gg][h]=PH[gg*4+h]+PH[(4+(gg>>1))*4+h]+((gg==h)?rn:0.0);
        inv4d(S4f,Sif);
        double Kr[4];
        for (int gg=0;gg<4;++gg){ double s=0;
            for (int h=0;h<4;++h) s+=PH[r*4+h]*Sif[h][gg]; Kr[gg]=s; }
#pragma unroll
        for (int c=0;c<6;++c){
            double s=P[r*6+c];
            for (int gg=0;gg<4;++gg) s-=Kr[gg]*PH[c*4+gg];
            tp[r*6+c]=0.0; tp[36+r*6+c]=s; tp[72+r*6+c]=0.0;
        }
    }
    __syncthreads();
    compose_smem((tid<72)?tid:-1, tp, sr, tr, wP);
    __syncthreads();

    if (tid == 0) {
        double ll=0.0;
        for (int i=0;i<16;++i) ll+=g_llp[i];
        sll=ll;
        double P6[6][6];
        for (int r=0;r<6;++r) for (int c=0;c<6;++c) P6[r][c]=tr[36+r*6+c];
        double aT0=1.0/(1.0/(double)bs[0]+2048.0/sig2);
        double aT1=1.0/(1.0/(double)bs[1]+2048.0/sig2);
        double a[4]={aT0,aT1,aT0,aT1};
        double B[4][4], C[4][2];
        for (int g=0;g<4;++g){
            for (int h=0;h<4;++h) B[g][h]=P6[g][h]-((g==h)?a[g]/32.0:0.0);
            C[g][0]=P6[g][4]; C[g][1]=P6[g][5];
        }
        double p00=P6[4][4], p02=P6[4][5], p22=P6[5][5];
        double La[4]={1.0/a[0],1.0/a[1],1.0/a[2],1.0/a[3]};
        double Xb[4][4];
        for (int g=0;g<4;++g) for (int h=0;h<4;++h)
            Xb[g][h]=((g==h)?1.0:0.0)+32.0*La[g]*B[g][h];
        double Yb[4][4]; inv4d(Xb,Yb);
        double G[4][4];
        for (int g=0;g<4;++g) for (int h=0;h<4;++h){
            double s=0; for (int k=0;k<4;++k) s+=B[g][k]*Yb[k][h];
            G[g][h]=La[g]*s*La[h];
        }
        double M4[4][4];
        for (int g=0;g<4;++g) for (int h=0;h<4;++h)
            M4[g][h]=((g==h)?La[g]:0.0)-32.0*G[g][h];
        double MC[4][2];
        for (int g=0;g<4;++g){
            double t0=0,t1=0;
            for (int k=0;k<4;++k){ t0+=M4[g][k]*C[k][0]; t1+=M4[g][k]*C[k][1]; }
            MC[g][0]=t0; MC[g][1]=t1;
        }
        double ss00=p00, ss01=p02, ss11=p22;
        for (int g=0;g<4;++g){
            ss00-=32.0*C[g][0]*MC[g][0];
            ss01-=32.0*C[g][0]*MC[g][1];
            ss11-=32.0*C[g][1]*MC[g][1];
        }
        {
            double det=ss00*ss11-ss01*ss01;
            double id=1.0/det;
            sSsInv[0][0]=ss11*id; sSsInv[0][1]=-ss01*id;
            sSsInv[1][0]=-ss01*id; sSsInv[1][1]=ss00*id;
        }
        for (int g=0;g<4;++g){
            sE[g][0]=-(MC[g][0]*sSsInv[0][0]+MC[g][1]*sSsInv[1][0]);
            sE[g][1]=-(MC[g][0]*sSsInv[0][1]+MC[g][1]*sSsInv[1][1]);
        }
        for (int g=0;g<4;++g) for (int h=0;h<4;++h)
            sPhi[g][h]=-G[g][h]-(sE[g][0]*MC[h][0]+sE[g][1]*MC[h][1]);
        for (int g=0;g<4;++g) sLam4[g]=La[g];
        {
            const double td=2048.0;
            double sum00=td/3.0+td*(td-1.0)/2.0+(td-1.0)*td*(2.0*td-1.0)/6.0;
            double sum01=td/2.0+td*(td-1.0)/2.0;
            double pu00=1.0+td*td+q*sum00;
            double pu01=td+q*sum01;
            double pu11=1.0+q*td;
            double det=pu00*pu11-pu01*pu01, idd=1.0/det;
            sPu[0]=pu11*idd; sPu[1]=-pu01*idd; sPu[2]=pu00*idd;
        }
    }
    __syncthreads();
    const int off = (out_size >= 17425) ? 1 : 0;
    if (tid == 0 && off) out[0] = (float)sll;
    for (int ecnt = tid; ecnt < 17424; ecnt += blockDim.x) {
        int r = ecnt / 132, c = ecnt % 132;
        double val = 0.0;
        if (r < 128 && c < 128) {
            int g=(r&1)+((r>=64)?2:0), h=(c&1)+((c>=64)?2:0);
            val=sPhi[g][h];
            if (r==c) val+=sLam4[g];
        } else if (r < 128) {
            int g=(r&1)+((r>=64)?2:0), j=c-128;
            if (j==0) val=sE[g][0]; else if (j==2) val=sE[g][1];
        } else if (c < 128) {
            int h=(c&1)+((c>=64)?2:0), i=r-128;
            if (i==0) val=sE[h][0]; else if (i==2) val=sE[h][1];
        } else {
            int i=r-128, j=c-128;
            if ((i==0||i==2)&&(j==0||j==2)) val=sSsInv[i>>1][j>>1];
            else if (i==1&&j==1) val=sPu[0];
            else if ((i==1&&j==3)||(i==3&&j==1)) val=sPu[1];
            else if (i==3&&j==3) val=sPu[2];
        }
        out[off+ecnt]=(float)val;
    }
}

extern "C" void kernel_launch(void* const* d_in, const int* in_sizes, int n_in,
                              void* d_out, int out_size) {
    const float* track       = (const float*)d_in[0];
    const float* bias_scales = (const float*)d_in[1];
    const float* obs_noise   = (const float*)d_in[2];
    const float* trans_noise = (const float*)d_in[3];
    float* out = (float*)d_out;
    init_elems<<<16,128>>>(track, bias_scales, obs_noise, trans_noise);
    int p = 0;
    for (int d=1; d<TS; d<<=1) { scan_level<<<52,256>>>(d, p); p^=1; }
    ll_terms<<<16,128>>>(track, bias_scales, obs_noise, trans_noise, p);
    cov_finalize<<<1,256>>>(bias_scales, obs_noise, trans_noise, out, out_size);
}

// round 17
// speedup vs baseline: 3.4663x; 1.1435x over previous
#include <cuda_runtime.h>
#include <math.h>

#define TS 2048
#define ESTR 160
// element layout (floats): A rows 8-padded at 0, C at 48, J at 96, b at 144, eta at 152
#define LOG2PI 1.8378770664093454836

__device__ float g_buf[2][TS*ESTR];
__device__ double g_llp[16];

__device__ __forceinline__ float inv4f(const float A[4][4], float R[4][4]) {
    float a00=A[0][0],a01=A[0][1],a02=A[0][2],a03=A[0][3];
    float a10=A[1][0],a11=A[1][1],a12=A[1][2],a13=A[1][3];
    float a20=A[2][0],a21=A[2][1],a22=A[2][2],a23=A[2][3];
    float a30=A[3][0],a31=A[3][1],a32=A[3][2],a33=A[3][3];
    float s0=a00*a11-a10*a01,s1=a00*a12-a10*a02,s2=a00*a13-a10*a03;
    float s3=a01*a12-a11*a02,s4=a01*a13-a11*a03,s5=a02*a13-a12*a03;
    float c5=a22*a33-a32*a23,c4=a21*a33-a31*a23,c3=a21*a32-a31*a22;
    float c2=a20*a33-a30*a23,c1=a20*a32-a30*a22,c0=a20*a31-a30*a21;
    float det=s0*c5-s1*c4+s2*c3+s3*c2-s4*c1+s5*c0;
    float id=__fdividef(1.0f,det);
    R[0][0]=( a11*c5-a12*c4+a13*c3)*id; R[0][1]=(-a01*c5+a02*c4-a03*c3)*id;
    R[0][2]=( a31*s5-a32*s4+a33*s3)*id; R[0][3]=(-a21*s5+a22*s4-a23*s3)*id;
    R[1][0]=(-a10*c5+a12*c2-a13*c1)*id; R[1][1]=( a00*c5-a02*c2+a03*c1)*id;
    R[1][2]=(-a30*s5+a32*s2-a33*s1)*id; R[1][3]=( a20*s5-a22*s2+a23*s1)*id;
    R[2][0]=( a10*c4-a11*c2+a13*c0)*id; R[2][1]=(-a00*c4+a01*c2-a03*c0)*id;
    R[2][2]=( a30*s4-a31*s2+a33*s0)*id; R[2][3]=(-a20*s4+a21*s2-a23*s0)*id;
    R[3][0]=(-a10*c3+a11*c1-a12*c0)*id; R[3][1]=( a00*c3-a01*c1+a02*c0)*id;
    R[3][2]=(-a30*s3+a31*s1-a32*s0)*id; R[3][3]=( a20*s3-a21*s1+a22*s0)*id;
    return det;
}

__device__ __forceinline__ double inv4d(const double A[4][4], double R[4][4]) {
    double a00=A[0][0],a01=A[0][1],a02=A[0][2],a03=A[0][3];
    double a10=A[1][0],a11=A[1][1],a12=A[1][2],a13=A[1][3];
    double a20=A[2][0],a21=A[2][1],a22=A[2][2],a23=A[2][3];
    double a30=A[3][0],a31=A[3][1],a32=A[3][2],a33=A[3][3];
    double s0=a00*a11-a10*a01,s1=a00*a12-a10*a02,s2=a00*a13-a10*a03;
    double s3=a01*a12-a11*a02,s4=a01*a13-a11*a03,s5=a02*a13-a12*a03;
    double c5=a22*a33-a32*a23,c4=a21*a33-a31*a23,c3=a21*a32-a31*a22;
    double c2=a20*a33-a30*a23,c1=a20*a32-a30*a22,c0=a20*a31-a30*a21;
    double det=s0*c5-s1*c4+s2*c3+s3*c2-s4*c1+s5*c0;
    double id=1.0/det;
    R[0][0]=( a11*c5-a12*c4+a13*c3)*id; R[0][1]=(-a01*c5+a02*c4-a03*c3)*id;
    R[0][2]=( a31*s5-a32*s4+a33*s3)*id; R[0][3]=(-a21*s5+a22*s4-a23*s3)*id;
    R[1][0]=(-a10*c5+a12*c2-a13*c1)*id; R[1][1]=( a00*c5-a02*c2+a03*c1)*id;
    R[1][2]=(-a30*s5+a32*s2-a33*s1)*id; R[1][3]=( a20*s5-a22*s2+a23*s1)*id;
    R[2][0]=( a10*c4-a11*c2+a13*c0)*id; R[2][1]=(-a00*c4+a01*c2-a03*c0)*id;
    R[2][2]=( a30*s4-a31*s2+a33*s0)*id; R[2][3]=(-a20*s4+a21*s2-a23*s0)*id;
    R[3][0]=(-a10*c3+a11*c1-a12*c0)*id; R[3][1]=( a00*c3-a01*c1+a02*c0)*id;
    R[3][2]=(-a30*s3+a31*s1-a32*s0)*id; R[3][3]=( a20*s3-a21*s1+a22*s0)*id;
    return det;
}

// Row-parallel Sarkka composition, unpivoted GJ (M = I + C1*J2 similar to SPD
// with eigenvalues >= 1).
template<typename T, bool VEC>
__device__ __forceinline__ void compose_rp(
    unsigned mask, int base, int r,
    const T* A1, const T* C1, const T* J1, const T* b1, const T* e1,
    const T* A2, const T* C2, const T* J2, const T* b2, const T* e2,
    T* Ao, T* Co, T* Jo, T* bo, T* eo)
{
    T M[12];
#pragma unroll
    for (int c=0;c<6;++c){
        T s=(r==c)?T(1):T(0);
#pragma unroll
        for (int k=0;k<6;++k) s += C1[k]*__shfl_sync(mask, J2[c], base+k);
        M[c]=s; M[6+c]=(r==c)?T(1):T(0);
    }
#pragma unroll
    for (int col=0;col<6;++col){
        T piv=__shfl_sync(mask, M[col], base+col);
        T ip=T(1)/piv;
        if (r==col){
#pragma unroll
            for (int j=0;j<12;++j) M[j]*=ip;
        }
        T f=M[col];
        T pr[12];
#pragma unroll
        for (int j=0;j<12;++j) pr[j]=__shfl_sync(mask, M[j], base+col);
        if (r!=col){
#pragma unroll
            for (int j=0;j<12;++j) M[j]-=f*pr[j];
        }
    }
    T D[6];
#pragma unroll
    for (int c=0;c<6;++c) D[c]=M[6+c];
    T T1[6];
#pragma unroll
    for (int c=0;c<6;++c){ T s=T(0);
#pragma unroll
        for (int k=0;k<6;++k) s+=D[k]*__shfl_sync(mask, A1[c], base+k);
        T1[c]=s; }
#pragma unroll
    for (int c=0;c<6;++c){ T s=T(0);
#pragma unroll
        for (int k=0;k<6;++k) s+=A2[k]*__shfl_sync(mask, T1[c], base+k);
        Ao[c]=s; }
    if (VEC) {
        T u[6], wv[6];
#pragma unroll
        for (int i=0;i<6;++i){ T s=b1[i];
#pragma unroll
            for (int k=0;k<6;++k) s+=__shfl_sync(mask, C1[k], base+i)*e2[k];
            u[i]=s; }
#pragma unroll
        for (int i=0;i<6;++i){ T s=T(0);
#pragma unroll
            for (int k=0;k<6;++k) s+=__shfl_sync(mask, D[k], base+i)*u[k];
            wv[i]=s; }
#pragma unroll
        for (int i=0;i<6;++i){ T s=b2[i];
#pragma unroll
            for (int k=0;k<6;++k) s+=__shfl_sync(mask, A2[k], base+i)*wv[k];
            bo[i]=s; }
        T rv[6];
#pragma unroll
        for (int k=0;k<6;++k){ T s=e2[k];
#pragma unroll
            for (int m=0;m<6;++m) s-=__shfl_sync(mask, J2[m], base+k)*b1[m];
            rv[k]=s; }
#pragma unroll
        for (int c=0;c<6;++c){ T s=e1[c];
#pragma unroll
            for (int k=0;k<6;++k) s+=__shfl_sync(mask, T1[c], base+k)*rv[k];
            eo[c]=s; }
    }
    T S[6], Tt[6];
#pragma unroll
    for (int c=0;c<6;++c){ T s=T(0);
#pragma unroll
        for (int k=0;k<6;++k) s+=D[k]*__shfl_sync(mask, C1[c], base+k);
        S[c]=s; }
#pragma unroll
    for (int c=0;c<6;++c){ T s=T(0);
#pragma unroll
        for (int k=0;k<6;++k) s+=A2[k]*__shfl_sync(mask, S[c], base+k);
        Tt[c]=s; }
#pragma unroll
    for (int c=0;c<6;++c){ T s=C2[c];
#pragma unroll
        for (int k=0;k<6;++k) s+=Tt[k]*__shfl_sync(mask, A2[k], base+c);
        Co[c]=s; }
    T T5[6];
#pragma unroll
    for (int c=0;c<6;++c){ T s=T(0);
#pragma unroll
        for (int k=0;k<6;++k) s+=J2[k]*__shfl_sync(mask, A1[c], base+k);
        T5[c]=s; }
    T T1t[6];
#pragma unroll
    for (int j=0;j<6;++j){
#pragma unroll
        for (int k=0;k<6;++k){
            T w2=__shfl_sync(mask, T1[j], base+k);
            if (r==j) T1t[k]=w2;
        }
    }
#pragma unroll
    for (int c=0;c<6;++c){ T s=J1[c];
#pragma unroll
        for (int k=0;k<6;++k) s+=T1t[k]*__shfl_sync(mask, T5[c], base+k);
        Jo[c]=s; }
}

// vectorized element row I/O (8-float padded rows)
__device__ __forceinline__ void load_rows(const float* e, int r,
    float* A, float* C, float* J) {
    float4 x; float2 y;
    x=*(const float4*)(e + r*8);        A[0]=x.x;A[1]=x.y;A[2]=x.z;A[3]=x.w;
    y=*(const float2*)(e + r*8 + 4);    A[4]=y.x;A[5]=y.y;
    x=*(const float4*)(e + 48 + r*8);   C[0]=x.x;C[1]=x.y;C[2]=x.z;C[3]=x.w;
    y=*(const float2*)(e + 48 + r*8+4); C[4]=y.x;C[5]=y.y;
    x=*(const float4*)(e + 96 + r*8);   J[0]=x.x;J[1]=x.y;J[2]=x.z;J[3]=x.w;
    y=*(const float2*)(e + 96 + r*8+4); J[4]=y.x;J[5]=y.y;
}
__device__ __forceinline__ void load_vecs(const float* e, float* b, float* et) {
    float4 x; float2 y;
    x=*(const float4*)(e + 144); b[0]=x.x;b[1]=x.y;b[2]=x.z;b[3]=x.w;
    y=*(const float2*)(e + 148); b[4]=y.x;b[5]=y.y;
    x=*(const float4*)(e + 152); et[0]=x.x;et[1]=x.y;et[2]=x.z;et[3]=x.w;
    y=*(const float2*)(e + 156); et[4]=y.x;et[5]=y.y;
}
__device__ __forceinline__ void store_rows(float* e, int r,
    const float* A, const float* C, const float* J) {
    *(float4*)(e + r*8)        = make_float4(A[0],A[1],A[2],A[3]);
    *(float2*)(e + r*8 + 4)    = make_float2(A[4],A[5]);
    *(float4*)(e + 48 + r*8)   = make_float4(C[0],C[1],C[2],C[3]);
    *(float2*)(e + 48 + r*8+4) = make_float2(C[4],C[5]);
    *(float4*)(e + 96 + r*8)   = make_float4(J[0],J[1],J[2],J[3]);
    *(float2*)(e + 96 + r*8+4) = make_float2(J[4],J[5]);
}
__device__ __forceinline__ void store_vecs(float* e, const float* b, const float* et) {
    *(float4*)(e + 144) = make_float4(b[0],b[1],b[2],b[3]);
    *(float2*)(e + 148) = make_float2(b[4],b[5]);
    *(float4*)(e + 152) = make_float4(et[0],et[1],et[2],et[3]);
    *(float2*)(e + 156) = make_float2(et[4],et[5]);
}

__global__ void init_elems(const float* __restrict__ track, const float* __restrict__ bs,
                           const float* __restrict__ onp, const float* __restrict__ tnp) {
    int t = blockIdx.x*blockDim.x + threadIdx.x;
    if (t >= TS) return;
    float* e = &g_buf[0][t*ESTR];
    for (int i=0;i<ESTR;++i) e[i]=0.0f;
    const float sig2 = onp[0]*onp[0];
    const float q = tnp[0]*tnp[0];
    const float rn = sig2/32.0f;
    float Qs[2][2] = {{q/3.0f, q*0.5f},{q*0.5f, q}};
    float y0 = track[2*t], y1 = track[2*t+1];
    float yb[4] = {y0,y1,y0,y1};
    if (t == 0) {
        float P[6][6];
        for (int r=0;r<6;++r) for (int c=0;c<6;++c) P[r][c]=0.0f;
        P[0][0]=bs[0]/32.0f; P[1][1]=bs[1]/32.0f;
        P[2][2]=P[0][0]; P[3][3]=P[1][1];
        P[4][4]=2.0f+Qs[0][0]; P[4][5]=1.0f+Qs[0][1];
        P[5][4]=1.0f+Qs[1][0]; P[5][5]=1.0f+Qs[1][1];
        float PH[6][4];
        for (int r=0;r<6;++r) for (int g=0;g<4;++g) PH[r][g]=P[r][g]+P[r][4+(g>>1)];
        float S4[4][4];
        for (int g=0;g<4;++g) for (int h=0;h<4;++h)
            S4[g][h]=PH[g][h]+PH[4+(g>>1)][h]+((g==h)?rn:0.0f);
        float Si[4][4]; inv4f(S4,Si);
        float K[6][4];
        for (int r=0;r<6;++r) for (int g=0;g<4;++g){
            float s=0; for (int h=0;h<4;++h) s+=PH[r][h]*Si[h][g]; K[r][g]=s; }
        for (int r=0;r<6;++r){ float s=0; for (int g=0;g<4;++g) s+=K[r][g]*yb[g]; e[144+r]=s; }
        float Cf[6][6];
        for (int r=0;r<6;++r) for (int c=0;c<6;++c){
            float s=P[r][c]; for (int g=0;g<4;++g) s-=K[r][g]*PH[c][g];
            Cf[r][c]=s;
        }
        for (int r=0;r<6;++r) for (int c=r+1;c<6;++c){
            float m=0.5f*(Cf[r][c]+Cf[c][r]); Cf[r][c]=m; Cf[c][r]=m; }
        for (int r=0;r<6;++r) for (int c=0;c<6;++c) e[48+r*8+c]=Cf[r][c];
        // A=0, J=0, eta=0 already
    } else {
        float S4[4][4];
        for (int g=0;g<4;++g) for (int h=0;h<4;++h)
            S4[g][h]=Qs[g>>1][h>>1]+((g==h)?rn:0.0f);
        float Si[4][4]; inv4f(S4,Si);
        float K2[2][4];
        for (int i=0;i<2;++i) for (int g=0;g<4;++g){
            float s=0; for (int h=0;h<4;++h) s+=Qs[i][h>>1]*Si[h][g]; K2[i][g]=s; }
        float A[6][6];
        for (int r=0;r<6;++r) for (int c=0;c<6;++c) A[r][c]=(r==c)?1.0f:0.0f;
        A[4][5]=1.0f;
        for (int i=0;i<2;++i){
            for (int g=0;g<4;++g) A[4+i][g]-=K2[i][g];
            float s4=K2[i][0]+K2[i][1];
            float s5=s4+K2[i][2]+K2[i][3];
            A[4+i][4]-=s4; A[4+i][5]-=s5;
        }
        float C2[2][2];
        for (int i=0;i<2;++i) for (int j=0;j<2;++j){
            float s=Qs[i][j];
            for (int g=0;g<4;++g) s-=K2[i][g]*Qs[g>>1][j];
            C2[i][j]=s;
        }
        { float m=0.5f*(C2[0][1]+C2[1][0]); C2[0][1]=m; C2[1][0]=m; }
        for (int i=0;i<2;++i){ float s=0; for (int g=0;g<4;++g) s+=K2[i][g]*yb[g]; e[144+4+i]=s; }
        float u[4];
        for (int g=0;g<4;++g){ float s=0; for (int h=0;h<4;++h) s+=Si[g][h]*yb[h]; u[g]=s; }
        e[152+0]=u[0]; e[152+1]=u[1]; e[152+2]=u[2]; e[152+3]=u[3];
        e[152+4]=u[0]+u[1]; e[152+5]=u[0]+u[1]+u[2]+u[3];
        float V[4][6];
        for (int g=0;g<4;++g){
            for (int d=0;d<4;++d) V[g][d]=Si[g][d];
            V[g][4]=Si[g][0]+Si[g][1];
            V[g][5]=Si[g][0]+Si[g][1]+Si[g][2]+Si[g][3];
        }
        for (int r=0;r<6;++r) for (int c=0;c<6;++c) e[r*8+c]=A[r][c];
        e[48+4*8+4]=C2[0][0]; e[48+4*8+5]=C2[0][1];
        e[48+5*8+4]=C2[1][0]; e[48+5*8+5]=C2[1][1];
        for (int c=0;c<4;++c) for (int d=0;d<6;++d) e[96+c*8+d]=V[c][d];
        for (int d=0;d<6;++d){
            e[96+4*8+d]=V[0][d]+V[1][d];
            e[96+5*8+d]=V[0][d]+V[1][d]+V[2][d]+V[3][d];
        }
    }
}

__global__ void __launch_bounds__(256) scan_level(int d, int srcp) {
    int lane = threadIdx.x & 31;
    int warp = threadIdx.x >> 5;
    if (lane >= 30) return;
    int g = lane/6, r = lane - g*6, base = g*6;
    unsigned mask = 0x3Fu << base;
    int gid = (blockIdx.x*8 + warp)*5 + g;
    if (gid >= TS) return;
    const float* sb = g_buf[srcp];
    float* db = g_buf[srcp^1];
    const float* ej = &sb[gid*ESTR];
    float* dst = &db[gid*ESTR];
    if (gid < d) {
#pragma unroll
        for (int mblk=0;mblk<3;++mblk){
            const float4* s4=(const float4*)(ej + mblk*48 + r*8);
            float4* d4=(float4*)(dst + mblk*48 + r*8);
            d4[0]=s4[0]; d4[1]=s4[1];
        }
        if (r==0){
            const float4* s4=(const float4*)(ej+144);
            float4* d4=(float4*)(dst+144);
            d4[0]=s4[0]; d4[1]=s4[1]; d4[2]=s4[2]; d4[3]=s4[3];
        }
        return;
    }
    const float* ei = &sb[(gid-d)*ESTR];
    float A1[6],C1[6],J1[6],b1[6],e1[6],A2[6],C2[6],J2[6],b2[6],e2[6];
    load_rows(ei, r, A1, C1, J1);
    load_rows(ej, r, A2, C2, J2);
    load_vecs(ei, b1, e1);
    load_vecs(ej, b2, e2);
    float Ao[6],Co[6],Jo[6],bo[6],eoo[6];
    compose_rp<float,true>(mask,base,r,A1,C1,J1,b1,e1,A2,C2,J2,b2,e2,Ao,Co,Jo,bo,eoo);
    store_rows(dst, r, Ao, Co, Jo);
    if (r==0) store_vecs(dst, bo, eoo);
}

__global__ void ll_terms(const float* __restrict__ track, const float* __restrict__ bs,
                         const float* __restrict__ onp, const float* __restrict__ tnp, int finp) {
    int t = blockIdx.x*blockDim.x + threadIdx.x;
    const double sig2 = (double)onp[0]*(double)onp[0];
    const double q = (double)tnp[0]*(double)tnp[0];
    const double rn = sig2/32.0;
    double llt = 0.0;
    if (t < TS) {
        double m[6], P[6][6];
        if (t == 0) {
            for (int i=0;i<6;++i) m[i]=0.0;
            for (int r=0;r<6;++r) for (int c=0;c<6;++c) P[r][c]=0.0;
            P[0][0]=(double)bs[0]/32.0; P[1][1]=(double)bs[1]/32.0;
            P[2][2]=P[0][0]; P[3][3]=P[1][1]; P[4][4]=1.0; P[5][5]=1.0;
        } else {
            const float* e = &g_buf[finp][(t-1)*ESTR];
            for (int i=0;i<6;++i) m[i]=(double)e[144+i];
            for (int r=0;r<6;++r) for (int c=0;c<6;++c) P[r][c]=(double)e[48+r*8+c];
        }
        double mp[6];
        for (int i=0;i<4;++i) mp[i]=m[i];
        mp[4]=m[4]+m[5]; mp[5]=m[5];
        for (int c=0;c<6;++c) P[4][c]+=P[5][c];
        for (int r=0;r<6;++r) P[r][4]+=P[r][5];
        P[4][4]+=q/3.0; P[4][5]+=q*0.5; P[5][4]+=q*0.5; P[5][5]+=q;
        double y0=(double)track[2*t], y1=(double)track[2*t+1];
        double yb[4]={y0,y1,y0,y1};
        double S4[4][4], v[4];
        for (int g=0;g<4;++g){
            int rg=g>>1;
            v[g]=yb[g]-(mp[g]+mp[4+rg]);
            for (int h=0;h<4;++h){
                int rh=h>>1;
                S4[g][h]=P[g][h]+P[g][4+rh]+P[4+rg][h]+P[4+rg][4+rh]+((g==h)?rn:0.0);
            }
        }
        double Si[4][4];
        double det=inv4d(S4,Si);
        double quad=0.0;
        for (int g=0;g<4;++g) for (int h=0;h<4;++h) quad+=v[g]*Si[g][h]*v[h];
        double tf=(double)t;
        double d0=1.0/(1.0/(double)bs[0]+tf/sig2)+sig2;
        double d1=1.0/(1.0/(double)bs[1]+tf/sig2)+sig2;
        double step=128.0*LOG2PI + 62.0*(log(d0)+log(d1))
                  + 4.0*log(32.0) + log(det) + quad;
        llt = -0.5*step;
    }
    __shared__ double sd[128];
    sd[threadIdx.x]=llt; __syncthreads();
    for (int s=64;s>0;s>>=1){ if((int)threadIdx.x<s) sd[threadIdx.x]+=sd[threadIdx.x+s]; __syncthreads(); }
    if (threadIdx.x==0) g_llp[blockIdx.x]=sd[0];
}

// shared-memory cooperative fp64 composition (A,C,J), unpivoted GJ,
// 3 barriers per column. E layout: [0:36) A, [36:72) C, [72:108) J.
// W: [0:72) augmented M, [72:108) T1, [108:144) T2, [144:180) T3, [181] recip.
// EVERY thread of the block must reach this from the SAME call site.
__device__ __forceinline__ void compose_smem(
    int lt, const double* E1, const double* E2, double* Eo, double* W)
{
    double* M  = W;
    double* T1 = W+72;
    double* T2 = W+108;
    double* T3 = W+144;
    const bool a72 = (lt >= 0 && lt < 72);
    const bool a36 = (lt >= 0 && lt < 36);
    int r12 = a72 ? lt/12 : 0, c12 = a72 ? lt%12 : 0;
    int r6  = a36 ? lt/6  : 0, c6  = a36 ? lt%6  : 0;
    int r6b = (lt>=36 && lt<72) ? (lt-36)/6 : 0, c6b = (lt>=36 && lt<72) ? (lt-36)%6 : 0;

    if (a72) {
        if (c12 < 6) {
            double s = (r12==c12)?1.0:0.0;
#pragma unroll
            for (int k=0;k<6;++k) s += E1[36+r12*6+k]*E2[72+k*6+c12];
            M[r12*12+c12] = s;
        } else {
            M[r12*12+c12] = (r12==(c12-6))?1.0:0.0;
        }
    }
    __syncthreads();
    for (int col=0; col<6; ++col) {
        if (lt == 0) W[181] = 1.0/M[col*12+col];
        __syncthreads();
        double f = a72 ? M[r12*12+col] : 0.0;  // pre-scale multiplier (row col unused)
        if (lt >= 0 && lt < 12) M[col*12+lt] *= W[181];
        __syncthreads();
        if (a72 && r12 != col) M[r12*12+c12] -= f*M[col*12+c12];
        __syncthreads();
    }
    if (a36) {
        double s=0;
#pragma unroll
        for (int k=0;k<6;++k) s += M[r6*12+6+k]*E1[k*6+c6];
        T1[r6*6+c6]=s;
    } else if (a72) {
        double s=0;
#pragma unroll
        for (int k=0;k<6;++k) s += E2[72+r6b*6+k]*E1[k*6+c6b];
        T2[r6b*6+c6b]=s;
    }
    __syncthreads();
    if (a36) {
        double s=0;
#pragma unroll
        for (int k=0;k<6;++k) s += E2[r6*6+k]*T1[k*6+c6];
        Eo[r6*6+c6]=s;
    } else if (a72) {
        double s=E1[72+r6b*6+c6b];
#pragma unroll
        for (int k=0;k<6;++k) s += T1[k*6+r6b]*T2[k*6+c6b];
        T3[r6b*6+c6b]=s;
    }
    __syncthreads();
    if (a36) {
        double s=0;
#pragma unroll
        for (int k=0;k<6;++k) s += M[r6*12+6+k]*E1[36+k*6+c6];
        T2[r6*6+c6]=s;
    } else if (a72) {
        Eo[72+r6b*6+c6b] = 0.5*(T3[r6b*6+c6b]+T3[c6b*6+r6b]);
    }
    __syncthreads();
    if (a36) {
        double s=0;
#pragma unroll
        for (int k=0;k<6;++k) s += E2[r6*6+k]*T2[k*6+c6];
        T1[r6*6+c6]=s;
    }
    __syncthreads();
    if (a36) {
        double s=E2[36+r6*6+c6];
#pragma unroll
        for (int k=0;k<6;++k) s += T1[r6*6+k]*E2[c6*6+k];
        T3[r6*6+c6]=s;
    }
    __syncthreads();
    if (a36) Eo[36+r6*6+c6] = 0.5*(T3[r6*6+c6]+T3[c6*6+r6]);
    __syncthreads();
}

// merged: fp64 binary powering + assembly + output
__global__ void __launch_bounds__(256)
cov_finalize(const float* __restrict__ bs, const float* __restrict__ onp,
             const float* __restrict__ tnp,
             float* __restrict__ out, int out_size) {
    __shared__ double sp[108], sr[108], tp[108], tr[108];
    __shared__ double wP[182], wR[182];
    __shared__ double sLam4[4], sPhi[4][4], sE[4][2], sSsInv[2][2], sPu[3];
    __shared__ double sll;
    int tid = threadIdx.x;
    const double sig2 = (double)onp[0]*(double)onp[0];
    const double q = (double)tnp[0]*(double)tnp[0];
    const double rn = sig2/32.0;
    double Qs[2][2]={{q/3.0,q*0.5},{q*0.5,q}};

    if (tid < 6) {
        int r=tid;
        double S4[4][4],Si[4][4];
        for (int gg=0;gg<4;++gg) for (int h=0;h<4;++h)
            S4[gg][h]=Qs[gg>>1][h>>1]+((gg==h)?rn:0.0);
        inv4d(S4,Si);
        double K2[2][4];
        for (int i=0;i<2;++i) for (int gg=0;gg<4;++gg){
            double s=0; for (int h=0;h<4;++h) s+=Qs[i][h>>1]*Si[h][gg]; K2[i][gg]=s; }
        double Ar[6];
#pragma unroll
        for (int c=0;c<6;++c) Ar[c]=(r==c)?1.0:0.0;
        if (r==4) Ar[5]=1.0;
        if (r>=4){
            int i=r-4;
            for (int gg=0; gg<4; ++gg) Ar[gg]-=K2[i][gg];
            double s4=K2[i][0]+K2[i][1], s5=s4+K2[i][2]+K2[i][3];
            Ar[4]-=s4; Ar[5]-=s5;
        }
        double C2m[2][2];
        for (int i=0;i<2;++i) for (int j=0;j<2;++j){
            double s=Qs[i][j];
            for (int gg=0;gg<4;++gg) s-=K2[i][gg]*Qs[gg>>1][j];
            C2m[i][j]=s;
        }
        { double m=0.5*(C2m[0][1]+C2m[1][0]); C2m[0][1]=m; C2m[1][0]=m; }
        double Cr[6]={0,0,0,0,0,0};
        if (r>=4){ Cr[4]=C2m[r-4][0]; Cr[5]=C2m[r-4][1]; }
        double V[4][6];
        for (int gg=0;gg<4;++gg){
            for (int d=0;d<4;++d) V[gg][d]=Si[gg][d];
            V[gg][4]=Si[gg][0]+Si[gg][1];
            V[gg][5]=V[gg][4]+Si[gg][2]+Si[gg][3];
        }
        double Jr[6];
#pragma unroll
        for (int c=0;c<6;++c){
            double s=0;
            for (int gg=0; gg<4; ++gg) if (r==gg) s=V[gg][c];
            if (r==4) s=V[0][c]+V[1][c];
            if (r==5) s=V[0][c]+V[1][c]+V[2][c]+V[3][c];
            Jr[c]=s;
        }
#pragma unroll
        for (int c=0;c<6;++c){
            sp[r*6+c]=Ar[c]; sp[36+r*6+c]=Cr[c]; sp[72+r*6+c]=Jr[c];
            sr[r*6+c]=(r==c)?1.0:0.0; sr[36+r*6+c]=0.0; sr[72+r*6+c]=0.0;
        }
    }
    __syncthreads();
    const bool isP = (tid < 72);
    int lt = isP ? tid : tid - 72;
    for (int it=0; it<11; ++it) {
        const double* E1s = isP ? sp : sr;
        double* Eos = isP ? tp : tr;
        double* Ws  = isP ? wP : wR;
        compose_smem(lt, E1s, sp, Eos, Ws);
        __syncthreads();
        if (tid < 108) sp[tid]=tp[tid];
        if (tid >= 36 && tid < 144) sr[tid-36]=tr[tid-36];
        __syncthreads();
    }
    if (tid < 6) {
        int r=tid;
        double P[36];
#pragma unroll
        for (int i=0;i<36;++i) P[i]=0.0;
        P[0]=(double)bs[0]/32.0; P[7]=(double)bs[1]/32.0;
        P[14]=P[0]; P[21]=P[7];
        P[4*6+4]=2.0+Qs[0][0]; P[4*6+5]=1.0+Qs[0][1];
        P[5*6+4]=1.0+Qs[0][1]; P[5*6+5]=1.0+Qs[1][1];
        double PH[24];
        for (int x=0;x<6;++x) for (int gg=0;gg<4;++gg) PH[x*4+gg]=P[x*6+gg]+P[x*6+4+(gg>>1)];
        double S4f[4][4], Sif[4][4];
        for (int gg=0;gg<4;++gg) for (int h=0;h<4;++h)
            S4f[gg][h]=PH[gg*4+h]+PH[(4+(gg>>1))*4+h]+((gg==h)?rn:0.0);
        inv4d(S4f,Sif);
        double Kr[4];
        for (int gg=0;gg<4;++gg){ double s=0;
            for (int h=0;h<4;++h) s+=PH[r*4+h]*Sif[h][gg]; Kr[gg]=s; }
#pragma unroll
        for (int c=0;c<6;++c){
            double s=P[r*6+c];
            for (int gg=0;gg<4;++gg) s-=Kr[gg]*PH[c*4+gg];
            tp[r*6+c]=0.0; tp[36+r*6+c]=s; tp[72+r*6+c]=0.0;
        }
    }
    __syncthreads();
    compose_smem((tid<72)?tid:-1, tp, sr, tr, wP);
    __syncthreads();

    if (tid == 0) {
        double ll=0.0;
        for (int i=0;i<16;++i) ll+=g_llp[i];
        sll=ll;
        double P6[6][6];
        for (int r=0;r<6;++r) for (int c=0;c<6;++c) P6[r][c]=tr[36+r*6+c];
        double aT0=1.0/(1.0/(double)bs[0]+2048.0/sig2);
        double aT1=1.0/(1.0/(double)bs[1]+2048.0/sig2);
        double a[4]={aT0,aT1,aT0,aT1};
        double B[4][4], C[4][2];
        for (int g=0;g<4;++g){
            for (int h=0;h<4;++h) B[g][h]=P6[g][h]-((g==h)?a[g]/32.0:0.0);
            C[g][0]=P6[g][4]; C[g][1]=P6[g][5];
        }
        double p00=P6[4][4], p02=P6[4][5], p22=P6[5][5];
        double La[4]={1.0/a[0],1.0/a[1],1.0/a[2],1.0/a[3]};
        double Xb[4][4];
        for (int g=0;g<4;++g) for (int h=0;h<4;++h)
            Xb[g][h]=((g==h)?1.0:0.0)+32.0*La[g]*B[g][h];
        double Yb[4][4]; inv4d(Xb,Yb);
        double G[4][4];
        for (int g=0;g<4;++g) for (int h=0;h<4;++h){
            double s=0; for (int k=0;k<4;++k) s+=B[g][k]*Yb[k][h];
            G[g][h]=La[g]*s*La[h];
        }
        double M4[4][4];
        for (int g=0;g<4;++g) for (int h=0;h<4;++h)
            M4[g][h]=((g==h)?La[g]:0.0)-32.0*G[g][h];
        double MC[4][2];
        for (int g=0;g<4;++g){
            double t0=0,t1=0;
            for (int k=0;k<4;++k){ t0+=M4[g][k]*C[k][0]; t1+=M4[g][k]*C[k][1]; }
            MC[g][0]=t0; MC[g][1]=t1;
        }
        double ss00=p00, ss01=p02, ss11=p22;
        for (int g=0;g<4;++g){
            ss00-=32.0*C[g][0]*MC[g][0];
            ss01-=32.0*C[g][0]*MC[g][1];
            ss11-=32.0*C[g][1]*MC[g][1];
        }
        {
            double det=ss00*ss11-ss01*ss01;
            double id=1.0/det;
            sSsInv[0][0]=ss11*id; sSsInv[0][1]=-ss01*id;
            sSsInv[1][0]=-ss01*id; sSsInv[1][1]=ss00*id;
        }
        for (int g=0;g<4;++g){
            sE[g][0]=-(MC[g][0]*sSsInv[0][0]+MC[g][1]*sSsInv[1][0]);
            sE[g][1]=-(MC[g][0]*sSsInv[0][1]+MC[g][1]*sSsInv[1][1]);
        }
        for (int g=0;g<4;++g) for (int h=0;h<4;++h)
            sPhi[g][h]=-G[g][h]-(sE[g][0]*MC[h][0]+sE[g][1]*MC[h][1]);
        for (int g=0;g<4;++g) sLam4[g]=La[g];
        {
            const double td=2048.0;
            double sum00=td/3.0+td*(td-1.0)/2.0+(td-1.0)*td*(2.0*td-1.0)/6.0;
            double sum01=td/2.0+td*(td-1.0)/2.0;
            double pu00=1.0+td*td+q*sum00;
            double pu01=td+q*sum01;
            double pu11=1.0+q*td;
            double det=pu00*pu11-pu01*pu01, idd=1.0/det;
            sPu[0]=pu11*idd; sPu[1]=-pu01*idd; sPu[2]=pu00*idd;
        }
    }
    __syncthreads();
    const int off = (out_size >= 17425) ? 1 : 0;
    if (tid == 0 && off) out[0] = (float)sll;
    for (int ecnt = tid; ecnt < 17424; ecnt += blockDim.x) {
        int r = ecnt / 132, c = ecnt % 132;
        double val = 0.0;
        if (r < 128 && c < 128) {
            int g=(r&1)+((r>=64)?2:0), h=(c&1)+((c>=64)?2:0);
            val=sPhi[g][h];
            if (r==c) val+=sLam4[g];
        } else if (r < 128) {
            int g=(r&1)+((r>=64)?2:0), j=c-128;
            if (j==0) val=sE[g][0]; else if (j==2) val=sE[g][1];
        } else if (c < 128) {
            int h=(c&1)+((c>=64)?2:0), i=r-128;
            if (i==0) val=sE[h][0]; else if (i==2) val=sE[h][1];
        } else {
            int i=r-128, j=c-128;
            if ((i==0||i==2)&&(j==0||j==2)) val=sSsInv[i>>1][j>>1];
            else if (i==1&&j==1) val=sPu[0];
            else if ((i==1&&j==3)||(i==3&&j==1)) val=sPu[1];
            else if (i==3&&j==3) val=sPu[2];
        }
        out[off+ecnt]=(float)val;
    }
}

extern "C" void kernel_launch(void* const* d_in, const int* in_sizes, int n_in,
                              void* d_out, int out_size) {
    const float* track       = (const float*)d_in[0];
    const float* bias_scales = (const float*)d_in[1];
    const float* obs_noise   = (const float*)d_in[2];
    const float* trans_noise = (const float*)d_in[3];
    float* out = (float*)d_out;
    init_elems<<<16,128>>>(track, bias_scales, obs_noise, trans_noise);
    int p = 0;
    for (int d=1; d<TS; d<<=1) { scan_level<<<52,256>>>(d, p); p^=1; }
    ll_terms<<<16,128>>>(track, bias_scales, obs_noise, trans_noise, p);
    cov_finalize<<<1,256>>>(bias_scales, obs_noise, trans_noise, out, out_size);
}